// round 2
// baseline (speedup 1.0000x reference)
#include <cuda_runtime.h>
#include <math.h>

#define S_LEN 4096
#define B_SZ  2
#define HD    128
#define DM    4096
#define NROWS (B_SZ * S_LEN)

// scratch for q, k, v (post-RoPE), [row][128] row-major, row = b*S + s
__device__ float g_q[NROWS * HD];
__device__ float g_k[NROWS * HD];
__device__ float g_v[NROWS * HD];

// ---------------------------------------------------------------------------
// Kernel A: QKV projection (C[8192,128] = X[8192,4096] * W^T) + fused RoPE
// blockIdx.y = z selects Wq/Wk/Wv. BM=64, BN=128, BK=16, 256 threads, 4x8 micro.
// ---------------------------------------------------------------------------
__global__ __launch_bounds__(256) void qkv_rope_kernel(
    const float* __restrict__ x,
    const float* __restrict__ Wq,
    const float* __restrict__ Wk,
    const float* __restrict__ Wv)
{
    const int z = blockIdx.y;
    const float* __restrict__ W   = (z == 0) ? Wq : (z == 1) ? Wk : Wv;
    float*       __restrict__ dst = (z == 0) ? g_q : (z == 1) ? g_k : g_v;
    const int m0 = blockIdx.x * 64;

    __shared__ float Xs[16][68];    // [k][m], padded
    __shared__ float Ws[16][132];   // [k][n], padded

    const int t  = threadIdx.x;
    const int tx = t & 15;          // n-tile: 16 threads * 8 cols
    const int ty = t >> 4;          // m-tile: 16 threads * 4 rows

    const int xr  = t >> 2;         // 0..63   row of X tile
    const int xs4 = (t & 3) * 4;    // k-seg
    const int wn  = t >> 1;         // 0..127  row of W
    const int wk8 = (t & 1) * 8;    // k-seg

    float acc[4][8];
#pragma unroll
    for (int i = 0; i < 4; i++)
#pragma unroll
        for (int j = 0; j < 8; j++) acc[i][j] = 0.f;

    const float* xp = x + (size_t)(m0 + xr) * DM + xs4;
    const float* wp = W + (size_t)wn * DM + wk8;

    for (int k0 = 0; k0 < DM; k0 += 16) {
        __syncthreads();
        float4 xv = *(const float4*)(xp + k0);
        Xs[xs4 + 0][xr] = xv.x;
        Xs[xs4 + 1][xr] = xv.y;
        Xs[xs4 + 2][xr] = xv.z;
        Xs[xs4 + 3][xr] = xv.w;
        float4 w0 = *(const float4*)(wp + k0);
        float4 w1 = *(const float4*)(wp + k0 + 4);
        Ws[wk8 + 0][wn] = w0.x;
        Ws[wk8 + 1][wn] = w0.y;
        Ws[wk8 + 2][wn] = w0.z;
        Ws[wk8 + 3][wn] = w0.w;
        Ws[wk8 + 4][wn] = w1.x;
        Ws[wk8 + 5][wn] = w1.y;
        Ws[wk8 + 6][wn] = w1.z;
        Ws[wk8 + 7][wn] = w1.w;
        __syncthreads();
#pragma unroll
        for (int k = 0; k < 16; k++) {
            float a[4], b[8];
            *(float4*)a       = *(const float4*)&Xs[k][ty * 4];
            *(float4*)(b)     = *(const float4*)&Ws[k][tx * 8];
            *(float4*)(b + 4) = *(const float4*)&Ws[k][tx * 8 + 4];
#pragma unroll
            for (int i = 0; i < 4; i++)
#pragma unroll
                for (int j = 0; j < 8; j++) acc[i][j] = fmaf(a[i], b[j], acc[i][j]);
        }
    }

    // epilogue: RoPE for q (z=0) and k (z=1), then store
#pragma unroll
    for (int i = 0; i < 4; i++) {
        const int row = m0 + ty * 4 + i;
        if (z < 2) {
            const float srow = (float)(row & (S_LEN - 1));   // s = row % S
#pragma unroll
            for (int pp = 0; pp < 4; pp++) {
                const int p = tx * 4 + pp;                   // pair index 0..63
                // theta = 10000^(-p/32) = 2^(-p * log2(1e4)/32)
                float theta = exp2f(-0.4152410118609203f * (float)p);
                float ang = srow * theta;
                float sn, cs;
                sincosf(ang, &sn, &cs);
                float v0 = acc[i][2 * pp], v1 = acc[i][2 * pp + 1];
                acc[i][2 * pp]     = v0 * cs - v1 * sn;
                acc[i][2 * pp + 1] = v1 * cs + v0 * sn;
            }
        }
        float4* o = (float4*)(dst + (size_t)row * HD + tx * 8);
        o[0] = make_float4(acc[i][0], acc[i][1], acc[i][2], acc[i][3]);
        o[1] = make_float4(acc[i][4], acc[i][5], acc[i][6], acc[i][7]);
    }
}

// ---------------------------------------------------------------------------
// Kernel B: causal flash attention, fp32.
// CTA: 64 queries (blockIdx.x), batch (blockIdx.y). 256 threads.
// Loop over 64-key tiles up to the diagonal. Online softmax.
// Smem: Qs/Ks transposed [d][m] (stride 68), Vs [j][n] (stride 132),
//       Sb = S^T then P^T [n][m] (stride 65), row stats.
// ---------------------------------------------------------------------------
#define QS_STR 68
#define VS_STR 132
#define SB_STR 65
#define ATTN_SMEM ((128 * QS_STR * 2 + 64 * VS_STR + 64 * SB_STR + 192) * 4)

__global__ __launch_bounds__(256) void attn_kernel(float* __restrict__ out)
{
    extern __shared__ float sm[];
    float* Qs   = sm;                          // [128][68]
    float* Ks   = Qs + 128 * QS_STR;           // [128][68]
    float* Vs   = Ks + 128 * QS_STR;           // [64][132]
    float* Sb   = Vs + 64 * VS_STR;            // [64][65]  S^T -> P^T
    float* rowM = Sb + 64 * SB_STR;            // [64]
    float* rowL = rowM + 64;                   // [64]
    float* rowA = rowL + 64;                   // [64] alpha

    const int b  = blockIdx.y;
    const int qt = blockIdx.x;
    const float* __restrict__ qb = g_q + (size_t)b * S_LEN * HD;
    const float* __restrict__ kb = g_k + (size_t)b * S_LEN * HD;
    const float* __restrict__ vb = g_v + (size_t)b * S_LEN * HD;

    const int t    = threadIdx.x;
    const int tx   = t & 15;
    const int ty   = t >> 4;
    const int lane = t & 31;
    const int warp = t >> 5;

    const float SCALE = 0.08838834764831845f;  // 1/sqrt(128)

    // load Q tile transposed into Qs[d][m]
    {
        const int qm = t & 63;
        const int s0 = t >> 6;                 // 0..3
#pragma unroll
        for (int r = 0; r < 8; r++) {
            int seg = s0 * 8 + r;              // 0..31 (float4 segment of d)
            float4 v = *(const float4*)(qb + (size_t)(qt * 64 + qm) * HD + seg * 4);
            Qs[(seg * 4 + 0) * QS_STR + qm] = v.x;
            Qs[(seg * 4 + 1) * QS_STR + qm] = v.y;
            Qs[(seg * 4 + 2) * QS_STR + qm] = v.z;
            Qs[(seg * 4 + 3) * QS_STR + qm] = v.w;
        }
    }
    if (t < 64) { rowM[t] = -INFINITY; rowL[t] = 0.f; }

    float o[4][8];
#pragma unroll
    for (int i = 0; i < 4; i++)
#pragma unroll
        for (int j = 0; j < 8; j++) o[i][j] = 0.f;

    for (int jt = 0; jt <= qt; jt++) {
        __syncthreads();   // previous PV done reading Ks/Vs
        // load K (transposed) and V tiles
        {
            const int kn = t & 63;
            const int s0 = t >> 6;
#pragma unroll
            for (int r = 0; r < 8; r++) {
                int seg = s0 * 8 + r;
                float4 vk = *(const float4*)(kb + (size_t)(jt * 64 + kn) * HD + seg * 4);
                Ks[(seg * 4 + 0) * QS_STR + kn] = vk.x;
                Ks[(seg * 4 + 1) * QS_STR + kn] = vk.y;
                Ks[(seg * 4 + 2) * QS_STR + kn] = vk.z;
                Ks[(seg * 4 + 3) * QS_STR + kn] = vk.w;
                float4 vv = *(const float4*)(vb + (size_t)(jt * 64 + kn) * HD + seg * 4);
                *(float4*)&Vs[kn * VS_STR + seg * 4] = vv;
            }
        }
        __syncthreads();

        // S = Q K^T : each thread 4x4
        float s[4][4];
#pragma unroll
        for (int i = 0; i < 4; i++)
#pragma unroll
            for (int j = 0; j < 4; j++) s[i][j] = 0.f;
        for (int d = 0; d < 128; d++) {
            float a[4], bb[4];
            *(float4*)a  = *(const float4*)&Qs[d * QS_STR + ty * 4];
            *(float4*)bb = *(const float4*)&Ks[d * QS_STR + tx * 4];
#pragma unroll
            for (int i = 0; i < 4; i++)
#pragma unroll
                for (int j = 0; j < 4; j++) s[i][j] = fmaf(a[i], bb[j], s[i][j]);
        }
        // store transposed: Sb[n][m]
#pragma unroll
        for (int i = 0; i < 4; i++)
#pragma unroll
            for (int j = 0; j < 4; j++)
                Sb[(tx * 4 + j) * SB_STR + ty * 4 + i] = s[i][j];
        __syncthreads();

        // online softmax: warp w owns rows w*8 .. w*8+7
#pragma unroll
        for (int r8 = 0; r8 < 8; r8++) {
            const int m  = warp * 8 + r8;
            const int mg = qt * 64 + m;
            float s0v = Sb[lane * SB_STR + m] * SCALE;
            float s1v = Sb[(lane + 32) * SB_STR + m] * SCALE;
            const bool v0 = (jt * 64 + lane)      <= mg;
            const bool v1 = (jt * 64 + lane + 32) <= mg;
            float mx = fmaxf(v0 ? s0v : -INFINITY, v1 ? s1v : -INFINITY);
#pragma unroll
            for (int off = 16; off > 0; off >>= 1)
                mx = fmaxf(mx, __shfl_xor_sync(0xFFFFFFFFu, mx, off));
            const float mold = rowM[m];
            const float mnew = fmaxf(mold, mx);
            float p0 = v0 ? __expf(s0v - mnew) : 0.f;
            float p1 = v1 ? __expf(s1v - mnew) : 0.f;
            float sum = p0 + p1;
#pragma unroll
            for (int off = 16; off > 0; off >>= 1)
                sum += __shfl_xor_sync(0xFFFFFFFFu, sum, off);
            if (lane == 0) {
                float alpha = __expf(mold - mnew);   // 0 when mold = -inf
                rowA[m] = alpha;
                rowL[m] = rowL[m] * alpha + sum;
                rowM[m] = mnew;
            }
            Sb[lane * SB_STR + m]        = p0;
            Sb[(lane + 32) * SB_STR + m] = p1;
        }
        __syncthreads();

        // rescale O, then O += P V
        float al[4];
#pragma unroll
        for (int i = 0; i < 4; i++) al[i] = rowA[ty * 4 + i];
#pragma unroll
        for (int i = 0; i < 4; i++)
#pragma unroll
            for (int j = 0; j < 8; j++) o[i][j] *= al[i];

        for (int jj = 0; jj < 64; jj++) {
            float pA[4];
#pragma unroll
            for (int i = 0; i < 4; i++) pA[i] = Sb[jj * SB_STR + ty * 4 + i];
            float vB[8];
            *(float4*)vB       = *(const float4*)&Vs[jj * VS_STR + tx * 8];
            *(float4*)(vB + 4) = *(const float4*)&Vs[jj * VS_STR + tx * 8 + 4];
#pragma unroll
            for (int i = 0; i < 4; i++)
#pragma unroll
                for (int j = 0; j < 8; j++) o[i][j] = fmaf(pA[i], vB[j], o[i][j]);
        }
    }

    // final normalize + write
    float inv[4];
#pragma unroll
    for (int i = 0; i < 4; i++) inv[i] = 1.0f / rowL[ty * 4 + i];
#pragma unroll
    for (int i = 0; i < 4; i++) {
        const int m = qt * 64 + ty * 4 + i;
        float4* op = (float4*)(out + ((size_t)b * S_LEN + m) * HD + tx * 8);
        op[0] = make_float4(o[i][0] * inv[i], o[i][1] * inv[i], o[i][2] * inv[i], o[i][3] * inv[i]);
        op[1] = make_float4(o[i][4] * inv[i], o[i][5] * inv[i], o[i][6] * inv[i], o[i][7] * inv[i]);
    }
}

// ---------------------------------------------------------------------------
extern "C" void kernel_launch(void* const* d_in, const int* in_sizes, int n_in,
                              void* d_out, int out_size)
{
    const float* x  = (const float*)d_in[0];
    const float* Wq = (const float*)d_in[1];
    const float* Wk = (const float*)d_in[2];
    const float* Wv = (const float*)d_in[3];
    float* out = (float*)d_out;

    cudaFuncSetAttribute(attn_kernel, cudaFuncAttributeMaxDynamicSharedMemorySize, ATTN_SMEM);

    qkv_rope_kernel<<<dim3(NROWS / 64, 3), 256>>>(x, Wq, Wk, Wv);
    attn_kernel<<<dim3(S_LEN / 64, B_SZ), 256, ATTN_SMEM>>>(out);
}

// round 6
// speedup vs baseline: 3.0583x; 3.0583x over previous
#include <cuda_runtime.h>
#include <cstdint>
#include <math.h>

#define S_LEN 4096
#define B_SZ  2
#define HD    128
#define DM    4096
#define NROWS (B_SZ * S_LEN)
#define NEGINF (-1e30f)

// scratch
__device__ float g_q[NROWS * HD];
__device__ float g_k[NROWS * HD];
__device__ float g_v[NROWS * HD];
__device__ float g_opart[2 * NROWS * HD];
__device__ float g_mpart[2 * NROWS];
__device__ float g_lpart[2 * NROWS];

// ---------------- portable tensor-core helpers (sm_80+ PTX) ----------------
__device__ __forceinline__ uint32_t f2tf(float x) {
    uint32_t r;
    asm("cvt.rna.tf32.f32 %0, %1;" : "=r"(r) : "f"(x));
    return r;
}
// D(16x8,f32) += A(16x8,tf32) * B(8x8,tf32)
__device__ __forceinline__ void mma8(float c[4], const uint32_t a[4], const uint32_t b[2]) {
    asm volatile(
        "mma.sync.aligned.m16n8k8.row.col.f32.tf32.tf32.f32 "
        "{%0,%1,%2,%3}, {%4,%5,%6,%7}, {%8,%9}, {%0,%1,%2,%3};"
        : "+f"(c[0]), "+f"(c[1]), "+f"(c[2]), "+f"(c[3])
        : "r"(a[0]), "r"(a[1]), "r"(a[2]), "r"(a[3]), "r"(b[0]), "r"(b[1]));
}

// ===========================================================================
// Kernel A: QKV projection C[8192,128] = X[8192,4096] * W^T via tf32 mma,
// fused RoPE epilogue. BM=128 (8 warps x m16), BN=128, BK=32. grid (64, 3).
// ===========================================================================
#define PJ_STR 40   // smem row stride (floats), %32 == 8 -> conflict-free frags

__global__ __launch_bounds__(256) void qkv_mma_kernel(
    const float* __restrict__ x,
    const float* __restrict__ Wq,
    const float* __restrict__ Wk,
    const float* __restrict__ Wv)
{
    __shared__ uint32_t Xs[128 * PJ_STR];   // [m][k] tf32
    __shared__ uint32_t Ws[128 * PJ_STR];   // [n][k] tf32

    const int t    = threadIdx.x;
    const int lane = t & 31;
    const int w    = t >> 5;
    const int g    = lane >> 2;   // groupID
    const int tg   = lane & 3;    // thread-in-group
    const int z    = blockIdx.y;
    const int m0   = blockIdx.x * 128;
    const float* __restrict__ Wm = (z == 0) ? Wq : (z == 1) ? Wk : Wv;
    float* __restrict__ dst      = (z == 0) ? g_q : (z == 1) ? g_k : g_v;

    int rowL[4], segL[4];
#pragma unroll
    for (int i = 0; i < 4; i++) {
        int idx = i * 256 + t;
        rowL[i] = idx >> 3;          // 0..127
        segL[i] = (idx & 7) * 4;     // 0,4,..28
    }

    float acc[16][4];
#pragma unroll
    for (int n = 0; n < 16; n++)
#pragma unroll
        for (int j = 0; j < 4; j++) acc[n][j] = 0.f;

    // prefetch chunk 0
    float4 xr4[4], wr4[4];
#pragma unroll
    for (int i = 0; i < 4; i++) {
        xr4[i] = *(const float4*)(x  + (size_t)(m0 + rowL[i]) * DM + segL[i]);
        wr4[i] = *(const float4*)(Wm + (size_t)rowL[i] * DM + segL[i]);
    }

    for (int kc = 0; kc < DM; kc += 32) {
        __syncthreads();
#pragma unroll
        for (int i = 0; i < 4; i++) {
            uint32_t* xp = &Xs[rowL[i] * PJ_STR + segL[i]];
            xp[0] = f2tf(xr4[i].x); xp[1] = f2tf(xr4[i].y);
            xp[2] = f2tf(xr4[i].z); xp[3] = f2tf(xr4[i].w);
            uint32_t* wp = &Ws[rowL[i] * PJ_STR + segL[i]];
            wp[0] = f2tf(wr4[i].x); wp[1] = f2tf(wr4[i].y);
            wp[2] = f2tf(wr4[i].z); wp[3] = f2tf(wr4[i].w);
        }
        __syncthreads();
        if (kc + 32 < DM) {
            const int kn = kc + 32;
#pragma unroll
            for (int i = 0; i < 4; i++) {
                xr4[i] = *(const float4*)(x  + (size_t)(m0 + rowL[i]) * DM + kn + segL[i]);
                wr4[i] = *(const float4*)(Wm + (size_t)rowL[i] * DM + kn + segL[i]);
            }
        }
#pragma unroll
        for (int k8 = 0; k8 < 4; k8++) {
            uint32_t a[4];
            const uint32_t* x0 = &Xs[(w * 16 + g)     * PJ_STR + k8 * 8];
            const uint32_t* x1 = &Xs[(w * 16 + g + 8) * PJ_STR + k8 * 8];
            a[0] = x0[tg]; a[1] = x1[tg]; a[2] = x0[tg + 4]; a[3] = x1[tg + 4];
#pragma unroll
            for (int n8 = 0; n8 < 16; n8++) {
                uint32_t bb[2];
                const uint32_t* wr = &Ws[(n8 * 8 + g) * PJ_STR + k8 * 8];
                bb[0] = wr[tg]; bb[1] = wr[tg + 4];
                mma8(acc[n8], a, bb);
            }
        }
    }

    // epilogue: RoPE (pairs are exactly cols 2p,2p+1 = c0,c1 / c2,c3) + store
    const int r0 = m0 + w * 16 + g;
    const int r1 = r0 + 8;
    if (z < 2) {
        const float s0 = (float)(r0 & (S_LEN - 1));
        const float s1 = (float)(r1 & (S_LEN - 1));
#pragma unroll
        for (int n8 = 0; n8 < 16; n8++) {
            const int p = n8 * 4 + tg;
            const float th = exp2f(-0.4152410118609203f * (float)p);
            float sn0, cs0, sn1, cs1;
            sincosf(s0 * th, &sn0, &cs0);
            sincosf(s1 * th, &sn1, &cs1);
            float a0 = acc[n8][0], a1 = acc[n8][1];
            acc[n8][0] = a0 * cs0 - a1 * sn0;
            acc[n8][1] = a1 * cs0 + a0 * sn0;
            float a2 = acc[n8][2], a3 = acc[n8][3];
            acc[n8][2] = a2 * cs1 - a3 * sn1;
            acc[n8][3] = a3 * cs1 + a2 * sn1;
        }
    }
#pragma unroll
    for (int n8 = 0; n8 < 16; n8++) {
        const int c = n8 * 8 + 2 * tg;
        *(float2*)(dst + (size_t)r0 * HD + c) = make_float2(acc[n8][0], acc[n8][1]);
        *(float2*)(dst + (size_t)r1 * HD + c) = make_float2(acc[n8][2], acc[n8][3]);
    }
}

// ===========================================================================
// Kernel B: causal flash attention, tf32 mma, register softmax.
// CTA = 128 queries (8 warps x m16) x 64-key tiles; 2-way KV split (blockIdx.z).
// Q fragments live in registers; P staged via warp-private smem for layout fix.
// ===========================================================================
#define KS_STR  72    // Ks [d:128][key:64], %32==8
#define VS_STR2 136   // Vs [key:64][hd:128], %32==8
#define PS_STR  72    // Ps per-warp [row:16][key:64], %32==8
#define ATT_SMEM ((128 * KS_STR + 64 * VS_STR2 + 8 * 16 * PS_STR) * 4)

__global__ __launch_bounds__(256) void attn_kernel()
{
    extern __shared__ uint32_t sm[];
    uint32_t* Ks = sm;                       // tf32 K^T tile
    uint32_t* Vs = Ks + 128 * KS_STR;        // tf32 V tile
    uint32_t* Ps = Vs + 64 * VS_STR2;        // tf32 P, per-warp slices

    const int t    = threadIdx.x;
    const int lane = t & 31;
    const int w    = t >> 5;
    const int g    = lane >> 2;
    const int tg   = lane & 3;
    const int b    = blockIdx.y;
    const int h    = blockIdx.z;
    const int qt   = (S_LEN / 128 - 1) - blockIdx.x;   // heavy CTAs first

    const float* __restrict__ qb = g_q + (size_t)b * S_LEN * HD;
    const float* __restrict__ kb = g_k + (size_t)b * S_LEN * HD;
    const float* __restrict__ vb = g_v + (size_t)b * S_LEN * HD;

    const float SCALE = 0.08838834764831845f;  // 1/sqrt(128)
    const int gr0 = qt * 128 + w * 16 + g;
    const int gr1 = gr0 + 8;

    // Q fragments (scale folded in), held in registers for the whole CTA
    uint32_t qf[16][4];
#pragma unroll
    for (int k8 = 0; k8 < 16; k8++) {
        const float* p0 = qb + (size_t)gr0 * HD + k8 * 8;
        const float* p1 = qb + (size_t)gr1 * HD + k8 * 8;
        qf[k8][0] = f2tf(p0[tg] * SCALE);
        qf[k8][1] = f2tf(p1[tg] * SCALE);
        qf[k8][2] = f2tf(p0[tg + 4] * SCALE);
        qf[k8][3] = f2tf(p1[tg + 4] * SCALE);
    }

    float of[16][4];
#pragma unroll
    for (int n = 0; n < 16; n++)
#pragma unroll
        for (int j = 0; j < 4; j++) of[n][j] = 0.f;
    float m0 = NEGINF, m1 = NEGINF, l0 = 0.f, l1 = 0.f;

    const int ntiles = 2 * qt + 2;
    const int j0 = h ? (qt + 1) : 0;
    const int j1 = h ? ntiles : (qt + 1);

    uint32_t* pw = &Ps[w * 16 * PS_STR];

    for (int jt = j0; jt < j1; jt++) {
        __syncthreads();
        // load K (transposed, tf32) and V (tf32) tiles
#pragma unroll
        for (int i = 0; i < 8; i++) {
            int idx = i * 256 + t;
            int key = idx & 63, seg = idx >> 6;   // seg 0..31 (float4 of d)
            float4 kv = *(const float4*)(kb + (size_t)(jt * 64 + key) * HD + seg * 4);
            Ks[(seg * 4 + 0) * KS_STR + key] = f2tf(kv.x);
            Ks[(seg * 4 + 1) * KS_STR + key] = f2tf(kv.y);
            Ks[(seg * 4 + 2) * KS_STR + key] = f2tf(kv.z);
            Ks[(seg * 4 + 3) * KS_STR + key] = f2tf(kv.w);
            float4 vv = *(const float4*)(vb + (size_t)(jt * 64 + key) * HD + seg * 4);
            uint32_t* vp = &Vs[key * VS_STR2 + seg * 4];
            vp[0] = f2tf(vv.x); vp[1] = f2tf(vv.y); vp[2] = f2tf(vv.z); vp[3] = f2tf(vv.w);
        }
        __syncthreads();

        // S = (Q*scale) K^T
        float sf[8][4];
#pragma unroll
        for (int n = 0; n < 8; n++)
#pragma unroll
            for (int j = 0; j < 4; j++) sf[n][j] = 0.f;
#pragma unroll
        for (int k8 = 0; k8 < 16; k8++) {
#pragma unroll
            for (int n8 = 0; n8 < 8; n8++) {
                uint32_t bb[2];
                const uint32_t* kp = &Ks[(k8 * 8 + tg) * KS_STR + n8 * 8 + g];
                bb[0] = kp[0];
                bb[1] = kp[4 * KS_STR];
                mma8(sf[n8], qf[k8], bb);
            }
        }

        // causal mask (only tiles that straddle the diagonal)
        if (jt >= 2 * qt) {
#pragma unroll
            for (int n8 = 0; n8 < 8; n8++) {
                const int c0 = jt * 64 + n8 * 8 + 2 * tg;
                const int c1 = c0 + 1;
                if (c0 > gr0) sf[n8][0] = NEGINF;
                if (c1 > gr0) sf[n8][1] = NEGINF;
                if (c0 > gr1) sf[n8][2] = NEGINF;
                if (c1 > gr1) sf[n8][3] = NEGINF;
            }
        }

        // row max (quad shuffle over the 4 threads holding the row)
        float mx0 = NEGINF, mx1 = NEGINF;
#pragma unroll
        for (int n8 = 0; n8 < 8; n8++) {
            mx0 = fmaxf(mx0, fmaxf(sf[n8][0], sf[n8][1]));
            mx1 = fmaxf(mx1, fmaxf(sf[n8][2], sf[n8][3]));
        }
        mx0 = fmaxf(mx0, __shfl_xor_sync(0xFFFFFFFFu, mx0, 1));
        mx0 = fmaxf(mx0, __shfl_xor_sync(0xFFFFFFFFu, mx0, 2));
        mx1 = fmaxf(mx1, __shfl_xor_sync(0xFFFFFFFFu, mx1, 1));
        mx1 = fmaxf(mx1, __shfl_xor_sync(0xFFFFFFFFu, mx1, 2));

        const float mn0 = fmaxf(m0, mx0);
        const float mn1 = fmaxf(m1, mx1);
        const float al0 = __expf(m0 - mn0);   // -1e30 sentinel -> exp underflows to 0
        const float al1 = __expf(m1 - mn1);

        // p = exp(s - m), sum
        float sum0 = 0.f, sum1 = 0.f;
#pragma unroll
        for (int n8 = 0; n8 < 8; n8++) {
            sf[n8][0] = __expf(sf[n8][0] - mn0);
            sf[n8][1] = __expf(sf[n8][1] - mn0);
            sf[n8][2] = __expf(sf[n8][2] - mn1);
            sf[n8][3] = __expf(sf[n8][3] - mn1);
            sum0 += sf[n8][0] + sf[n8][1];
            sum1 += sf[n8][2] + sf[n8][3];
        }
        sum0 += __shfl_xor_sync(0xFFFFFFFFu, sum0, 1);
        sum0 += __shfl_xor_sync(0xFFFFFFFFu, sum0, 2);
        sum1 += __shfl_xor_sync(0xFFFFFFFFu, sum1, 1);
        sum1 += __shfl_xor_sync(0xFFFFFFFFu, sum1, 2);
        l0 = l0 * al0 + sum0; m0 = mn0;
        l1 = l1 * al1 + sum1; m1 = mn1;

        // stage P into warp-private smem (C-layout write, A-layout read)
#pragma unroll
        for (int n8 = 0; n8 < 8; n8++) {
            uint2 pk0 = make_uint2(f2tf(sf[n8][0]), f2tf(sf[n8][1]));
            *(uint2*)&pw[g * PS_STR + n8 * 8 + 2 * tg] = pk0;
            uint2 pk1 = make_uint2(f2tf(sf[n8][2]), f2tf(sf[n8][3]));
            *(uint2*)&pw[(g + 8) * PS_STR + n8 * 8 + 2 * tg] = pk1;
        }
        __syncwarp();

        // rescale O
#pragma unroll
        for (int n8 = 0; n8 < 16; n8++) {
            of[n8][0] *= al0; of[n8][1] *= al0;
            of[n8][2] *= al1; of[n8][3] *= al1;
        }

        // O += P V
#pragma unroll
        for (int k8 = 0; k8 < 8; k8++) {
            uint32_t af[4];
            af[0] = pw[g * PS_STR + k8 * 8 + tg];
            af[1] = pw[(g + 8) * PS_STR + k8 * 8 + tg];
            af[2] = pw[g * PS_STR + k8 * 8 + tg + 4];
            af[3] = pw[(g + 8) * PS_STR + k8 * 8 + tg + 4];
#pragma unroll
            for (int n8 = 0; n8 < 16; n8++) {
                uint32_t bb[2];
                const uint32_t* vp = &Vs[(k8 * 8 + tg) * VS_STR2 + n8 * 8 + g];
                bb[0] = vp[0];
                bb[1] = vp[4 * VS_STR2];
                mma8(of[n8], af, bb);
            }
        }
    }

    // write partials (normalized by own l) + stats
    const float inv0 = (l0 > 0.f) ? 1.0f / l0 : 0.f;
    const float inv1 = (l1 > 0.f) ? 1.0f / l1 : 0.f;
    float* ob = g_opart + ((size_t)h * NROWS + (size_t)b * S_LEN) * HD;
#pragma unroll
    for (int n8 = 0; n8 < 16; n8++) {
        const int c = n8 * 8 + 2 * tg;
        *(float2*)(ob + (size_t)gr0 * HD + c) = make_float2(of[n8][0] * inv0, of[n8][1] * inv0);
        *(float2*)(ob + (size_t)gr1 * HD + c) = make_float2(of[n8][2] * inv1, of[n8][3] * inv1);
    }
    if (tg == 0) {
        const int base = h * NROWS + b * S_LEN;
        g_mpart[base + gr0] = m0; g_lpart[base + gr0] = l0;
        g_mpart[base + gr1] = m1; g_lpart[base + gr1] = l1;
    }
}

// ===========================================================================
// Kernel C: combine the 2 partial-softmax halves.
// ===========================================================================
__global__ __launch_bounds__(256) void combine_kernel(float* __restrict__ out)
{
    const int idx = blockIdx.x * 256 + threadIdx.x;   // NROWS*32 float4 slots
    const int row = idx >> 5;
    const int c4  = idx & 31;
    const float m0 = g_mpart[row],         l0 = g_lpart[row];
    const float m1 = g_mpart[NROWS + row], l1 = g_lpart[NROWS + row];
    const float M  = fmaxf(m0, m1);
    const float w0 = l0 * __expf(m0 - M);   // sentinel m -> weight 0
    const float w1 = l1 * __expf(m1 - M);
    const float inv = 1.0f / (w0 + w1);
    const size_t off = ((size_t)row << 7) + (c4 << 2);
    const float4 a  = *(const float4*)(g_opart + off);
    const float4 bb = *(const float4*)(g_opart + (size_t)NROWS * HD + off);
    float4 r;
    r.x = (w0 * a.x + w1 * bb.x) * inv;
    r.y = (w0 * a.y + w1 * bb.y) * inv;
    r.z = (w0 * a.z + w1 * bb.z) * inv;
    r.w = (w0 * a.w + w1 * bb.w) * inv;
    *(float4*)(out + off) = r;
}

// ===========================================================================
extern "C" void kernel_launch(void* const* d_in, const int* in_sizes, int n_in,
                              void* d_out, int out_size)
{
    const float* x  = (const float*)d_in[0];
    const float* Wq = (const float*)d_in[1];
    const float* Wk = (const float*)d_in[2];
    const float* Wv = (const float*)d_in[3];
    float* out = (float*)d_out;

    cudaFuncSetAttribute(attn_kernel, cudaFuncAttributeMaxDynamicSharedMemorySize, ATT_SMEM);

    qkv_mma_kernel<<<dim3(NROWS / 128, 3), 256>>>(x, Wq, Wk, Wv);
    attn_kernel<<<dim3(S_LEN / 128, B_SZ, 2), 256, ATT_SMEM>>>();
    combine_kernel<<<(NROWS * 32) / 256, 256>>>(out);
}

// round 7
// speedup vs baseline: 3.3339x; 1.0901x over previous
#include <cuda_runtime.h>
#include <cstdint>
#include <math.h>

#define S_LEN 4096
#define B_SZ  2
#define HD    128
#define DM    4096
#define NROWS (B_SZ * S_LEN)
#define NEGINF (-1e30f)
#define NSPLIT 4

// scratch
__device__ float g_q[NROWS * HD];
__device__ float g_k[NROWS * HD];
__device__ float g_v[NROWS * HD];
__device__ float g_opart[NSPLIT * NROWS * HD];
__device__ float g_mpart[NSPLIT * NROWS];
__device__ float g_lpart[NSPLIT * NROWS];

// ---------------- portable tensor-core helpers (sm_80+ PTX) ----------------
__device__ __forceinline__ uint32_t f2tf(float x) {
    uint32_t r;
    asm("cvt.rna.tf32.f32 %0, %1;" : "=r"(r) : "f"(x));
    return r;
}
// D(16x8,f32) += A(16x8,tf32) * B(8x8,tf32)
__device__ __forceinline__ void mma8(float c[4], const uint32_t a[4], const uint32_t b[2]) {
    asm volatile(
        "mma.sync.aligned.m16n8k8.row.col.f32.tf32.tf32.f32 "
        "{%0,%1,%2,%3}, {%4,%5,%6,%7}, {%8,%9}, {%0,%1,%2,%3};"
        : "+f"(c[0]), "+f"(c[1]), "+f"(c[2]), "+f"(c[3])
        : "r"(a[0]), "r"(a[1]), "r"(a[2]), "r"(a[3]), "r"(b[0]), "r"(b[1]));
}

// ===========================================================================
// Kernel A: QKV projection C[8192,128] = X[8192,4096] * W^T via tf32 mma,
// fused RoPE epilogue. BM=128 (8 warps x m16), BN=128, BK=32, 2 CTAs/SM.
// Smem packs mma fragment pairs (k, k+4) adjacently -> 64-bit fragment loads.
// Word layout: [row][k8*8 + 2*tg + half], row stride PJW=36 (16 data uint2 + pad).
// ===========================================================================
#define PJW 36

__global__ __launch_bounds__(256, 2) void qkv_mma_kernel(
    const float* __restrict__ x,
    const float* __restrict__ Wq,
    const float* __restrict__ Wk,
    const float* __restrict__ Wv)
{
    __shared__ uint32_t Xs[128 * PJW];
    __shared__ uint32_t Ws[128 * PJW];

    const int t    = threadIdx.x;
    const int lane = t & 31;
    const int w    = t >> 5;
    const int g    = lane >> 2;   // groupID
    const int tg   = lane & 3;    // thread-in-group
    const int z    = blockIdx.y;
    const int m0   = blockIdx.x * 128;
    const float* __restrict__ Wm = (z == 0) ? Wq : (z == 1) ? Wk : Wv;
    float* __restrict__ dst      = (z == 0) ? g_q : (z == 1) ? g_k : g_v;

    // per-thread load mapping: 4 items of (row, seg) covering 128 rows x 8 segs
    int rowL[4], segL[4];
    uint32_t sbase[4];
#pragma unroll
    for (int i = 0; i < 4; i++) {
        int idx = i * 256 + t;
        rowL[i]  = idx >> 3;                          // 0..127
        segL[i]  = idx & 7;                           // 0..7 (float4 seg of BK=32)
        sbase[i] = rowL[i] * PJW + (segL[i] >> 1) * 8 + (segL[i] & 1);
    }

    float acc[16][4];
#pragma unroll
    for (int n = 0; n < 16; n++)
#pragma unroll
        for (int j = 0; j < 4; j++) acc[n][j] = 0.f;

    const uint32_t ar0 = (w * 16 + g) * PJW;
    const uint32_t ar1 = (w * 16 + g + 8) * PJW;

    for (int kc = 0; kc < DM; kc += 32) {
        __syncthreads();
#pragma unroll
        for (int i = 0; i < 4; i++) {
            const float4 xv = *(const float4*)(x  + (size_t)(m0 + rowL[i]) * DM + kc + segL[i] * 4);
            uint32_t* xp = &Xs[sbase[i]];
            xp[0] = f2tf(xv.x); xp[2] = f2tf(xv.y); xp[4] = f2tf(xv.z); xp[6] = f2tf(xv.w);
            const float4 wv = *(const float4*)(Wm + (size_t)rowL[i] * DM + kc + segL[i] * 4);
            uint32_t* wp = &Ws[sbase[i]];
            wp[0] = f2tf(wv.x); wp[2] = f2tf(wv.y); wp[4] = f2tf(wv.z); wp[6] = f2tf(wv.w);
        }
        __syncthreads();
#pragma unroll
        for (int k8 = 0; k8 < 4; k8++) {
            const uint2 u0 = *(const uint2*)&Xs[ar0 + k8 * 8 + 2 * tg];
            const uint2 u1 = *(const uint2*)&Xs[ar1 + k8 * 8 + 2 * tg];
            uint32_t a[4] = {u0.x, u1.x, u0.y, u1.y};
#pragma unroll
            for (int n8 = 0; n8 < 16; n8++) {
                const uint2 ub = *(const uint2*)&Ws[(n8 * 8 + g) * PJW + k8 * 8 + 2 * tg];
                uint32_t bb[2] = {ub.x, ub.y};
                mma8(acc[n8], a, bb);
            }
        }
    }

    // epilogue: RoPE (pairs are exactly cols 2p,2p+1 = c0,c1 / c2,c3) + store
    const int r0 = m0 + w * 16 + g;
    const int r1 = r0 + 8;
    if (z < 2) {
        const float s0 = (float)(r0 & (S_LEN - 1));
        const float s1 = (float)(r1 & (S_LEN - 1));
#pragma unroll
        for (int n8 = 0; n8 < 16; n8++) {
            const int p = n8 * 4 + tg;
            const float th = exp2f(-0.4152410118609203f * (float)p);
            float sn0, cs0, sn1, cs1;
            sincosf(s0 * th, &sn0, &cs0);
            sincosf(s1 * th, &sn1, &cs1);
            float a0 = acc[n8][0], a1 = acc[n8][1];
            acc[n8][0] = a0 * cs0 - a1 * sn0;
            acc[n8][1] = a1 * cs0 + a0 * sn0;
            float a2 = acc[n8][2], a3 = acc[n8][3];
            acc[n8][2] = a2 * cs1 - a3 * sn1;
            acc[n8][3] = a3 * cs1 + a2 * sn1;
        }
    }
#pragma unroll
    for (int n8 = 0; n8 < 16; n8++) {
        const int c = n8 * 8 + 2 * tg;
        *(float2*)(dst + (size_t)r0 * HD + c) = make_float2(acc[n8][0], acc[n8][1]);
        *(float2*)(dst + (size_t)r1 * HD + c) = make_float2(acc[n8][2], acc[n8][3]);
    }
}

// ===========================================================================
// Kernel B: causal flash attention, tf32 mma, register softmax.
// CTA = 128 queries (8 warps x m16); 4-way KV split (blockIdx.z).
// ===========================================================================
#define KS_STR  72    // Ks [d:128][key:64], %32==8
#define VS_STR2 136   // Vs [key:64][hd:128], %32==8
#define PS_STR  72    // Ps per-warp [row:16][key:64], %32==8
#define ATT_SMEM ((128 * KS_STR + 64 * VS_STR2 + 8 * 16 * PS_STR) * 4)

__global__ __launch_bounds__(256) void attn_kernel()
{
    extern __shared__ uint32_t sm[];
    uint32_t* Ks = sm;                       // tf32 K^T tile
    uint32_t* Vs = Ks + 128 * KS_STR;        // tf32 V tile
    uint32_t* Ps = Vs + 64 * VS_STR2;        // tf32 P, per-warp slices

    const int t    = threadIdx.x;
    const int lane = t & 31;
    const int w    = t >> 5;
    const int g    = lane >> 2;
    const int tg   = lane & 3;
    const int b    = blockIdx.y;
    const int h    = blockIdx.z;
    const int qt   = (S_LEN / 128 - 1) - blockIdx.x;   // heavy CTAs first

    const int gr0 = qt * 128 + w * 16 + g;
    const int gr1 = gr0 + 8;
    const int statbase = h * NROWS + b * S_LEN;

    // split [0, ntiles) into NSPLIT chunks
    const int ntiles = 2 * qt + 2;
    const int cs = (ntiles + NSPLIT - 1) / NSPLIT;
    const int j0 = h * cs;
    const int j1 = min(ntiles, j0 + cs);
    if (j0 >= j1) {      // empty split: stats only (weight 0 in combine)
        if (tg == 0) {
            g_mpart[statbase + gr0] = NEGINF; g_lpart[statbase + gr0] = 0.f;
            g_mpart[statbase + gr1] = NEGINF; g_lpart[statbase + gr1] = 0.f;
        }
        return;
    }

    const float* __restrict__ qb = g_q + (size_t)b * S_LEN * HD;
    const float* __restrict__ kb = g_k + (size_t)b * S_LEN * HD;
    const float* __restrict__ vb = g_v + (size_t)b * S_LEN * HD;

    const float SCALE = 0.08838834764831845f;  // 1/sqrt(128)

    // Q fragments (scale folded in), held in registers for the whole CTA
    uint32_t qf[16][4];
#pragma unroll
    for (int k8 = 0; k8 < 16; k8++) {
        const float* p0 = qb + (size_t)gr0 * HD + k8 * 8;
        const float* p1 = qb + (size_t)gr1 * HD + k8 * 8;
        qf[k8][0] = f2tf(p0[tg] * SCALE);
        qf[k8][1] = f2tf(p1[tg] * SCALE);
        qf[k8][2] = f2tf(p0[tg + 4] * SCALE);
        qf[k8][3] = f2tf(p1[tg + 4] * SCALE);
    }

    float of[16][4];
#pragma unroll
    for (int n = 0; n < 16; n++)
#pragma unroll
        for (int j = 0; j < 4; j++) of[n][j] = 0.f;
    float m0 = NEGINF, m1 = NEGINF, l0 = 0.f, l1 = 0.f;

    uint32_t* pw = &Ps[w * 16 * PS_STR];

    for (int jt = j0; jt < j1; jt++) {
        __syncthreads();
        // load K (transposed, tf32) and V (tf32) tiles
#pragma unroll
        for (int i = 0; i < 8; i++) {
            int idx = i * 256 + t;
            int key = idx & 63, seg = idx >> 6;   // seg 0..31 (float4 of d)
            float4 kv = *(const float4*)(kb + (size_t)(jt * 64 + key) * HD + seg * 4);
            Ks[(seg * 4 + 0) * KS_STR + key] = f2tf(kv.x);
            Ks[(seg * 4 + 1) * KS_STR + key] = f2tf(kv.y);
            Ks[(seg * 4 + 2) * KS_STR + key] = f2tf(kv.z);
            Ks[(seg * 4 + 3) * KS_STR + key] = f2tf(kv.w);
            float4 vv = *(const float4*)(vb + (size_t)(jt * 64 + key) * HD + seg * 4);
            uint32_t* vp = &Vs[key * VS_STR2 + seg * 4];
            vp[0] = f2tf(vv.x); vp[1] = f2tf(vv.y); vp[2] = f2tf(vv.z); vp[3] = f2tf(vv.w);
        }
        __syncthreads();

        // S = (Q*scale) K^T
        float sf[8][4];
#pragma unroll
        for (int n = 0; n < 8; n++)
#pragma unroll
            for (int j = 0; j < 4; j++) sf[n][j] = 0.f;
#pragma unroll
        for (int k8 = 0; k8 < 16; k8++) {
#pragma unroll
            for (int n8 = 0; n8 < 8; n8++) {
                uint32_t bb[2];
                const uint32_t* kp = &Ks[(k8 * 8 + tg) * KS_STR + n8 * 8 + g];
                bb[0] = kp[0];
                bb[1] = kp[4 * KS_STR];
                mma8(sf[n8], qf[k8], bb);
            }
        }

        // causal mask (only tiles that straddle the diagonal)
        if (jt >= 2 * qt) {
#pragma unroll
            for (int n8 = 0; n8 < 8; n8++) {
                const int c0 = jt * 64 + n8 * 8 + 2 * tg;
                const int c1 = c0 + 1;
                if (c0 > gr0) sf[n8][0] = NEGINF;
                if (c1 > gr0) sf[n8][1] = NEGINF;
                if (c0 > gr1) sf[n8][2] = NEGINF;
                if (c1 > gr1) sf[n8][3] = NEGINF;
            }
        }

        // row max (quad shuffle over the 4 threads holding the row)
        float mx0 = NEGINF, mx1 = NEGINF;
#pragma unroll
        for (int n8 = 0; n8 < 8; n8++) {
            mx0 = fmaxf(mx0, fmaxf(sf[n8][0], sf[n8][1]));
            mx1 = fmaxf(mx1, fmaxf(sf[n8][2], sf[n8][3]));
        }
        mx0 = fmaxf(mx0, __shfl_xor_sync(0xFFFFFFFFu, mx0, 1));
        mx0 = fmaxf(mx0, __shfl_xor_sync(0xFFFFFFFFu, mx0, 2));
        mx1 = fmaxf(mx1, __shfl_xor_sync(0xFFFFFFFFu, mx1, 1));
        mx1 = fmaxf(mx1, __shfl_xor_sync(0xFFFFFFFFu, mx1, 2));

        const float mn0 = fmaxf(m0, mx0);
        const float mn1 = fmaxf(m1, mx1);
        const float al0 = __expf(m0 - mn0);   // -1e30 sentinel -> exp underflows to 0
        const float al1 = __expf(m1 - mn1);

        // p = exp(s - m), sum
        float sum0 = 0.f, sum1 = 0.f;
#pragma unroll
        for (int n8 = 0; n8 < 8; n8++) {
            sf[n8][0] = __expf(sf[n8][0] - mn0);
            sf[n8][1] = __expf(sf[n8][1] - mn0);
            sf[n8][2] = __expf(sf[n8][2] - mn1);
            sf[n8][3] = __expf(sf[n8][3] - mn1);
            sum0 += sf[n8][0] + sf[n8][1];
            sum1 += sf[n8][2] + sf[n8][3];
        }
        sum0 += __shfl_xor_sync(0xFFFFFFFFu, sum0, 1);
        sum0 += __shfl_xor_sync(0xFFFFFFFFu, sum0, 2);
        sum1 += __shfl_xor_sync(0xFFFFFFFFu, sum1, 1);
        sum1 += __shfl_xor_sync(0xFFFFFFFFu, sum1, 2);
        l0 = l0 * al0 + sum0; m0 = mn0;
        l1 = l1 * al1 + sum1; m1 = mn1;

        // stage P into warp-private smem (C-layout write, A-layout read)
#pragma unroll
        for (int n8 = 0; n8 < 8; n8++) {
            uint2 pk0 = make_uint2(f2tf(sf[n8][0]), f2tf(sf[n8][1]));
            *(uint2*)&pw[g * PS_STR + n8 * 8 + 2 * tg] = pk0;
            uint2 pk1 = make_uint2(f2tf(sf[n8][2]), f2tf(sf[n8][3]));
            *(uint2*)&pw[(g + 8) * PS_STR + n8 * 8 + 2 * tg] = pk1;
        }
        __syncwarp();

        // rescale O
#pragma unroll
        for (int n8 = 0; n8 < 16; n8++) {
            of[n8][0] *= al0; of[n8][1] *= al0;
            of[n8][2] *= al1; of[n8][3] *= al1;
        }

        // O += P V
#pragma unroll
        for (int k8 = 0; k8 < 8; k8++) {
            uint32_t af[4];
            af[0] = pw[g * PS_STR + k8 * 8 + tg];
            af[1] = pw[(g + 8) * PS_STR + k8 * 8 + tg];
            af[2] = pw[g * PS_STR + k8 * 8 + tg + 4];
            af[3] = pw[(g + 8) * PS_STR + k8 * 8 + tg + 4];
#pragma unroll
            for (int n8 = 0; n8 < 16; n8++) {
                uint32_t bb[2];
                const uint32_t* vp = &Vs[(k8 * 8 + tg) * VS_STR2 + n8 * 8 + g];
                bb[0] = vp[0];
                bb[1] = vp[4 * VS_STR2];
                mma8(of[n8], af, bb);
            }
        }
    }

    // write partials (normalized by own l) + stats
    const float inv0 = (l0 > 0.f) ? 1.0f / l0 : 0.f;
    const float inv1 = (l1 > 0.f) ? 1.0f / l1 : 0.f;
    float* ob = g_opart + ((size_t)h * NROWS + (size_t)b * S_LEN) * HD;
#pragma unroll
    for (int n8 = 0; n8 < 16; n8++) {
        const int c = n8 * 8 + 2 * tg;
        *(float2*)(ob + (size_t)gr0 * HD + c) = make_float2(of[n8][0] * inv0, of[n8][1] * inv0);
        *(float2*)(ob + (size_t)gr1 * HD + c) = make_float2(of[n8][2] * inv1, of[n8][3] * inv1);
    }
    if (tg == 0) {
        g_mpart[statbase + gr0] = m0; g_lpart[statbase + gr0] = l0;
        g_mpart[statbase + gr1] = m1; g_lpart[statbase + gr1] = l1;
    }
}

// ===========================================================================
// Kernel C: combine the NSPLIT partial-softmax results.
// ===========================================================================
__global__ __launch_bounds__(256) void combine_kernel(float* __restrict__ out)
{
    const int idx = blockIdx.x * 256 + threadIdx.x;   // NROWS*32 float4 slots
    const int row = idx >> 5;
    const int c4  = idx & 31;

    float mh[NSPLIT], lh[NSPLIT];
    float M = NEGINF;
#pragma unroll
    for (int h = 0; h < NSPLIT; h++) {
        mh[h] = g_mpart[h * NROWS + row];
        lh[h] = g_lpart[h * NROWS + row];
        M = fmaxf(M, mh[h]);
    }
    float wsum = 0.f, wh[NSPLIT];
#pragma unroll
    for (int h = 0; h < NSPLIT; h++) {
        wh[h] = lh[h] * __expf(mh[h] - M);   // l=0 split -> weight 0
        wsum += wh[h];
    }
    const float inv = 1.0f / wsum;

    const size_t off = ((size_t)row << 7) + (c4 << 2);
    float4 r = make_float4(0.f, 0.f, 0.f, 0.f);
#pragma unroll
    for (int h = 0; h < NSPLIT; h++) {
        const float wn = wh[h] * inv;
        if (wn > 0.f) {
            const float4 a = *(const float4*)(g_opart + (size_t)h * NROWS * HD + off);
            r.x += wn * a.x; r.y += wn * a.y; r.z += wn * a.z; r.w += wn * a.w;
        }
    }
    *(float4*)(out + off) = r;
}

// ===========================================================================
extern "C" void kernel_launch(void* const* d_in, const int* in_sizes, int n_in,
                              void* d_out, int out_size)
{
    const float* x  = (const float*)d_in[0];
    const float* Wq = (const float*)d_in[1];
    const float* Wk = (const float*)d_in[2];
    const float* Wv = (const float*)d_in[3];
    float* out = (float*)d_out;

    cudaFuncSetAttribute(attn_kernel, cudaFuncAttributeMaxDynamicSharedMemorySize, ATT_SMEM);

    qkv_mma_kernel<<<dim3(NROWS / 128, 3), 256>>>(x, Wq, Wk, Wv);
    attn_kernel<<<dim3(S_LEN / 128, B_SZ, NSPLIT), 256, ATT_SMEM>>>();
    combine_kernel<<<(NROWS * 32) / 256, 256>>>(out);
}

// round 8
// speedup vs baseline: 4.6267x; 1.3878x over previous
#include <cuda_runtime.h>
#include <cstdint>
#include <math.h>

#define S_LEN 4096
#define B_SZ  2
#define HD    128
#define DM    4096
#define NROWS (B_SZ * S_LEN)
#define NEGINF (-1e30f)
#define NSPLIT 4

// scratch
__device__ float g_q[NROWS * HD];
__device__ float g_k[NROWS * HD];
__device__ float g_v[NROWS * HD];
__device__ float g_opart[NSPLIT * NROWS * HD];
__device__ float g_mpart[NSPLIT * NROWS];
__device__ float g_lpart[NSPLIT * NROWS];

// ---------------- portable tensor-core helpers (sm_80+ PTX) ----------------
__device__ __forceinline__ uint32_t f2tf(float x) {
    uint32_t r;
    asm("cvt.rna.tf32.f32 %0, %1;" : "=r"(r) : "f"(x));
    return r;
}
// D(16x8,f32) += A(16x8,tf32) * B(8x8,tf32)
__device__ __forceinline__ void mma8(float c[4], const uint32_t a[4], const uint32_t b[2]) {
    asm volatile(
        "mma.sync.aligned.m16n8k8.row.col.f32.tf32.tf32.f32 "
        "{%0,%1,%2,%3}, {%4,%5,%6,%7}, {%8,%9}, {%0,%1,%2,%3};"
        : "+f"(c[0]), "+f"(c[1]), "+f"(c[2]), "+f"(c[3])
        : "r"(a[0]), "r"(a[1]), "r"(a[2]), "r"(a[3]), "r"(b[0]), "r"(b[1]));
}

// ===========================================================================
// Kernel A: QKV projection C[8192,128] = X[8192,4096] * W^T via tf32 mma,
// fused RoPE epilogue. BM=128, BN=128, BK=32.
// Warp grid 4(m) x 2(n): each warp owns an m32 x n64 tile (2 m-frags x 8 n-frags)
// -> B fragments amortized over 2 MMAs; 96 LDS words / thread / chunk.
// Register prefetch of the next K-chunk hides LDG latency under the MMA phase.
// ===========================================================================
#define PJW 36   // smem row stride in words; bank(addr) = (4*row + k) % 32

__global__ __launch_bounds__(256) void qkv_mma_kernel(
    const float* __restrict__ x,
    const float* __restrict__ Wq,
    const float* __restrict__ Wk,
    const float* __restrict__ Wv)
{
    __shared__ uint32_t Xs[128 * PJW];   // [m][k] tf32
    __shared__ uint32_t Ws[128 * PJW];   // [n][k] tf32

    const int t    = threadIdx.x;
    const int lane = t & 31;
    const int w    = t >> 5;
    const int g    = lane >> 2;   // groupID
    const int tg   = lane & 3;    // thread-in-group
    const int wm   = w & 3;       // m-warp 0..3  (rows wm*32 .. +31)
    const int wn   = w >> 2;      // n-warp 0..1  (cols wn*64 .. +63)
    const int z    = blockIdx.y;
    const int m0   = blockIdx.x * 128;
    const float* __restrict__ Wm = (z == 0) ? Wq : (z == 1) ? Wk : Wv;
    float* __restrict__ dst      = (z == 0) ? g_q : (z == 1) ? g_k : g_v;

    // per-thread load mapping: 4 items of (row, seg) covering 128 rows x 8 segs
    int rowL[4], segL[4];
    uint32_t sbase[4];
#pragma unroll
    for (int i = 0; i < 4; i++) {
        int idx = i * 256 + t;
        rowL[i]  = idx >> 3;                 // 0..127
        segL[i]  = idx & 7;                  // float4 seg of BK=32
        sbase[i] = rowL[i] * PJW + segL[i] * 4;
    }

    float acc[16][4];                        // [mf*8 + n8][..]
#pragma unroll
    for (int n = 0; n < 16; n++)
#pragma unroll
        for (int j = 0; j < 4; j++) acc[n][j] = 0.f;

    // prefetch chunk 0
    float4 xr[4], wr[4];
#pragma unroll
    for (int i = 0; i < 4; i++) {
        xr[i] = *(const float4*)(x  + (size_t)(m0 + rowL[i]) * DM + segL[i] * 4);
        wr[i] = *(const float4*)(Wm + (size_t)rowL[i] * DM + segL[i] * 4);
    }

    const uint32_t am0 = (wm * 32 + g) * PJW;          // m-frag 0, rows g / g+8
    const uint32_t am1 = (wm * 32 + 16 + g) * PJW;     // m-frag 1
    const uint32_t bn0 = (wn * 64 + g) * PJW;          // b rows n8*8+g

    for (int kc = 0; kc < DM; kc += 32) {
        __syncthreads();   // previous mma phase done reading smem
#pragma unroll
        for (int i = 0; i < 4; i++) {
            uint4 ux = make_uint4(f2tf(xr[i].x), f2tf(xr[i].y), f2tf(xr[i].z), f2tf(xr[i].w));
            *(uint4*)&Xs[sbase[i]] = ux;
            uint4 uw = make_uint4(f2tf(wr[i].x), f2tf(wr[i].y), f2tf(wr[i].z), f2tf(wr[i].w));
            *(uint4*)&Ws[sbase[i]] = uw;
        }
        __syncthreads();
        if (kc + 32 < DM) {   // prefetch next chunk; consumed after the mma phase
            const int kn = kc + 32;
#pragma unroll
            for (int i = 0; i < 4; i++) {
                xr[i] = *(const float4*)(x  + (size_t)(m0 + rowL[i]) * DM + kn + segL[i] * 4);
                wr[i] = *(const float4*)(Wm + (size_t)rowL[i] * DM + kn + segL[i] * 4);
            }
        }
#pragma unroll
        for (int k8 = 0; k8 < 4; k8++) {
            const int ko = k8 * 8 + tg;
            uint32_t a0[4], a1[4];
            a0[0] = Xs[am0 + ko];           a0[1] = Xs[am0 + 8 * PJW + ko];
            a0[2] = Xs[am0 + ko + 4];       a0[3] = Xs[am0 + 8 * PJW + ko + 4];
            a1[0] = Xs[am1 + ko];           a1[1] = Xs[am1 + 8 * PJW + ko];
            a1[2] = Xs[am1 + ko + 4];       a1[3] = Xs[am1 + 8 * PJW + ko + 4];
#pragma unroll
            for (int n8 = 0; n8 < 8; n8++) {
                uint32_t bb[2];
                const uint32_t* wp = &Ws[bn0 + n8 * 8 * PJW + ko];
                bb[0] = wp[0];
                bb[1] = wp[4];
                mma8(acc[n8],     a0, bb);
                mma8(acc[8 + n8], a1, bb);
            }
        }
    }

    // epilogue: RoPE (pairs are exactly cols 2p,2p+1) + store
    // warp rows: wm*32 + mf*16 + g (+8); cols: wn*64 + n8*8 + 2*tg (+1)
#pragma unroll
    for (int mf = 0; mf < 2; mf++) {
        const int r0 = m0 + wm * 32 + mf * 16 + g;
        const int r1 = r0 + 8;
        if (z < 2) {
            const float s0 = (float)(r0 & (S_LEN - 1));
            const float s1 = (float)(r1 & (S_LEN - 1));
#pragma unroll
            for (int n8 = 0; n8 < 8; n8++) {
                float* a = acc[mf * 8 + n8];
                const int p = wn * 32 + n8 * 4 + tg;
                const float th = exp2f(-0.4152410118609203f * (float)p);
                float sn0, cs0, sn1, cs1;
                sincosf(s0 * th, &sn0, &cs0);
                sincosf(s1 * th, &sn1, &cs1);
                float a0 = a[0], a1 = a[1];
                a[0] = a0 * cs0 - a1 * sn0;
                a[1] = a1 * cs0 + a0 * sn0;
                float a2 = a[2], a3 = a[3];
                a[2] = a2 * cs1 - a3 * sn1;
                a[3] = a3 * cs1 + a2 * sn1;
            }
        }
#pragma unroll
        for (int n8 = 0; n8 < 8; n8++) {
            const float* a = acc[mf * 8 + n8];
            const int c = wn * 64 + n8 * 8 + 2 * tg;
            *(float2*)(dst + (size_t)r0 * HD + c) = make_float2(a[0], a[1]);
            *(float2*)(dst + (size_t)r1 * HD + c) = make_float2(a[2], a[3]);
        }
    }
}

// ===========================================================================
// Kernel B: causal flash attention, tf32 mma, register softmax.
// CTA = 128 queries (8 warps x m16); 4-way KV split (blockIdx.z).
// ===========================================================================
#define KS_STR  72    // Ks [d:128][key:64], %32==8
#define VS_STR2 136   // Vs [key:64][hd:128], %32==8
#define PS_STR  72    // Ps per-warp [row:16][key:64], %32==8
#define ATT_SMEM ((128 * KS_STR + 64 * VS_STR2 + 8 * 16 * PS_STR) * 4)

__global__ __launch_bounds__(256) void attn_kernel()
{
    extern __shared__ uint32_t sm[];
    uint32_t* Ks = sm;                       // tf32 K^T tile
    uint32_t* Vs = Ks + 128 * KS_STR;        // tf32 V tile
    uint32_t* Ps = Vs + 64 * VS_STR2;        // tf32 P, per-warp slices

    const int t    = threadIdx.x;
    const int lane = t & 31;
    const int w    = t >> 5;
    const int g    = lane >> 2;
    const int tg   = lane & 3;
    const int b    = blockIdx.y;
    const int h    = blockIdx.z;
    const int qt   = (S_LEN / 128 - 1) - blockIdx.x;   // heavy CTAs first

    const int gr0 = qt * 128 + w * 16 + g;
    const int gr1 = gr0 + 8;
    const int statbase = h * NROWS + b * S_LEN;

    // split [0, ntiles) into NSPLIT chunks
    const int ntiles = 2 * qt + 2;
    const int cs = (ntiles + NSPLIT - 1) / NSPLIT;
    const int j0 = h * cs;
    const int j1 = min(ntiles, j0 + cs);
    if (j0 >= j1) {      // empty split: stats only (weight 0 in combine)
        if (tg == 0) {
            g_mpart[statbase + gr0] = NEGINF; g_lpart[statbase + gr0] = 0.f;
            g_mpart[statbase + gr1] = NEGINF; g_lpart[statbase + gr1] = 0.f;
        }
        return;
    }

    const float* __restrict__ qb = g_q + (size_t)b * S_LEN * HD;
    const float* __restrict__ kb = g_k + (size_t)b * S_LEN * HD;
    const float* __restrict__ vb = g_v + (size_t)b * S_LEN * HD;

    const float SCALE = 0.08838834764831845f;  // 1/sqrt(128)

    // Q fragments (scale folded in), held in registers for the whole CTA
    uint32_t qf[16][4];
#pragma unroll
    for (int k8 = 0; k8 < 16; k8++) {
        const float* p0 = qb + (size_t)gr0 * HD + k8 * 8;
        const float* p1 = qb + (size_t)gr1 * HD + k8 * 8;
        qf[k8][0] = f2tf(p0[tg] * SCALE);
        qf[k8][1] = f2tf(p1[tg] * SCALE);
        qf[k8][2] = f2tf(p0[tg + 4] * SCALE);
        qf[k8][3] = f2tf(p1[tg + 4] * SCALE);
    }

    float of[16][4];
#pragma unroll
    for (int n = 0; n < 16; n++)
#pragma unroll
        for (int j = 0; j < 4; j++) of[n][j] = 0.f;
    float m0 = NEGINF, m1 = NEGINF, l0 = 0.f, l1 = 0.f;

    uint32_t* pw = &Ps[w * 16 * PS_STR];

    for (int jt = j0; jt < j1; jt++) {
        __syncthreads();
        // load K (transposed, tf32) and V (tf32) tiles
#pragma unroll
        for (int i = 0; i < 8; i++) {
            int idx = i * 256 + t;
            int key = idx & 63, seg = idx >> 6;   // seg 0..31 (float4 of d)
            float4 kv = *(const float4*)(kb + (size_t)(jt * 64 + key) * HD + seg * 4);
            Ks[(seg * 4 + 0) * KS_STR + key] = f2tf(kv.x);
            Ks[(seg * 4 + 1) * KS_STR + key] = f2tf(kv.y);
            Ks[(seg * 4 + 2) * KS_STR + key] = f2tf(kv.z);
            Ks[(seg * 4 + 3) * KS_STR + key] = f2tf(kv.w);
            float4 vv = *(const float4*)(vb + (size_t)(jt * 64 + key) * HD + seg * 4);
            uint32_t* vp = &Vs[key * VS_STR2 + seg * 4];
            vp[0] = f2tf(vv.x); vp[1] = f2tf(vv.y); vp[2] = f2tf(vv.z); vp[3] = f2tf(vv.w);
        }
        __syncthreads();

        // S = (Q*scale) K^T
        float sf[8][4];
#pragma unroll
        for (int n = 0; n < 8; n++)
#pragma unroll
            for (int j = 0; j < 4; j++) sf[n][j] = 0.f;
#pragma unroll
        for (int k8 = 0; k8 < 16; k8++) {
#pragma unroll
            for (int n8 = 0; n8 < 8; n8++) {
                uint32_t bb[2];
                const uint32_t* kp = &Ks[(k8 * 8 + tg) * KS_STR + n8 * 8 + g];
                bb[0] = kp[0];
                bb[1] = kp[4 * KS_STR];
                mma8(sf[n8], qf[k8], bb);
            }
        }

        // causal mask (only tiles that straddle the diagonal)
        if (jt >= 2 * qt) {
#pragma unroll
            for (int n8 = 0; n8 < 8; n8++) {
                const int c0 = jt * 64 + n8 * 8 + 2 * tg;
                const int c1 = c0 + 1;
                if (c0 > gr0) sf[n8][0] = NEGINF;
                if (c1 > gr0) sf[n8][1] = NEGINF;
                if (c0 > gr1) sf[n8][2] = NEGINF;
                if (c1 > gr1) sf[n8][3] = NEGINF;
            }
        }

        // row max (quad shuffle over the 4 threads holding the row)
        float mx0 = NEGINF, mx1 = NEGINF;
#pragma unroll
        for (int n8 = 0; n8 < 8; n8++) {
            mx0 = fmaxf(mx0, fmaxf(sf[n8][0], sf[n8][1]));
            mx1 = fmaxf(mx1, fmaxf(sf[n8][2], sf[n8][3]));
        }
        mx0 = fmaxf(mx0, __shfl_xor_sync(0xFFFFFFFFu, mx0, 1));
        mx0 = fmaxf(mx0, __shfl_xor_sync(0xFFFFFFFFu, mx0, 2));
        mx1 = fmaxf(mx1, __shfl_xor_sync(0xFFFFFFFFu, mx1, 1));
        mx1 = fmaxf(mx1, __shfl_xor_sync(0xFFFFFFFFu, mx1, 2));

        const float mn0 = fmaxf(m0, mx0);
        const float mn1 = fmaxf(m1, mx1);
        const float al0 = __expf(m0 - mn0);   // -1e30 sentinel -> exp underflows to 0
        const float al1 = __expf(m1 - mn1);

        // p = exp(s - m), sum
        float sum0 = 0.f, sum1 = 0.f;
#pragma unroll
        for (int n8 = 0; n8 < 8; n8++) {
            sf[n8][0] = __expf(sf[n8][0] - mn0);
            sf[n8][1] = __expf(sf[n8][1] - mn0);
            sf[n8][2] = __expf(sf[n8][2] - mn1);
            sf[n8][3] = __expf(sf[n8][3] - mn1);
            sum0 += sf[n8][0] + sf[n8][1];
            sum1 += sf[n8][2] + sf[n8][3];
        }
        sum0 += __shfl_xor_sync(0xFFFFFFFFu, sum0, 1);
        sum0 += __shfl_xor_sync(0xFFFFFFFFu, sum0, 2);
        sum1 += __shfl_xor_sync(0xFFFFFFFFu, sum1, 1);
        sum1 += __shfl_xor_sync(0xFFFFFFFFu, sum1, 2);
        l0 = l0 * al0 + sum0; m0 = mn0;
        l1 = l1 * al1 + sum1; m1 = mn1;

        // stage P into warp-private smem (C-layout write, A-layout read)
#pragma unroll
        for (int n8 = 0; n8 < 8; n8++) {
            uint2 pk0 = make_uint2(f2tf(sf[n8][0]), f2tf(sf[n8][1]));
            *(uint2*)&pw[g * PS_STR + n8 * 8 + 2 * tg] = pk0;
            uint2 pk1 = make_uint2(f2tf(sf[n8][2]), f2tf(sf[n8][3]));
            *(uint2*)&pw[(g + 8) * PS_STR + n8 * 8 + 2 * tg] = pk1;
        }
        __syncwarp();

        // rescale O
#pragma unroll
        for (int n8 = 0; n8 < 16; n8++) {
            of[n8][0] *= al0; of[n8][1] *= al0;
            of[n8][2] *= al1; of[n8][3] *= al1;
        }

        // O += P V
#pragma unroll
        for (int k8 = 0; k8 < 8; k8++) {
            uint32_t af[4];
            af[0] = pw[g * PS_STR + k8 * 8 + tg];
            af[1] = pw[(g + 8) * PS_STR + k8 * 8 + tg];
            af[2] = pw[g * PS_STR + k8 * 8 + tg + 4];
            af[3] = pw[(g + 8) * PS_STR + k8 * 8 + tg + 4];
#pragma unroll
            for (int n8 = 0; n8 < 16; n8++) {
                uint32_t bb[2];
                const uint32_t* vp = &Vs[(k8 * 8 + tg) * VS_STR2 + n8 * 8 + g];
                bb[0] = vp[0];
                bb[1] = vp[4 * VS_STR2];
                mma8(of[n8], af, bb);
            }
        }
    }

    // write partials (normalized by own l) + stats
    const float inv0 = (l0 > 0.f) ? 1.0f / l0 : 0.f;
    const float inv1 = (l1 > 0.f) ? 1.0f / l1 : 0.f;
    float* ob = g_opart + ((size_t)h * NROWS + (size_t)b * S_LEN) * HD;
#pragma unroll
    for (int n8 = 0; n8 < 16; n8++) {
        const int c = n8 * 8 + 2 * tg;
        *(float2*)(ob + (size_t)gr0 * HD + c) = make_float2(of[n8][0] * inv0, of[n8][1] * inv0);
        *(float2*)(ob + (size_t)gr1 * HD + c) = make_float2(of[n8][2] * inv1, of[n8][3] * inv1);
    }
    if (tg == 0) {
        g_mpart[statbase + gr0] = m0; g_lpart[statbase + gr0] = l0;
        g_mpart[statbase + gr1] = m1; g_lpart[statbase + gr1] = l1;
    }
}

// ===========================================================================
// Kernel C: combine the NSPLIT partial-softmax results.
// ===========================================================================
__global__ __launch_bounds__(256) void combine_kernel(float* __restrict__ out)
{
    const int idx = blockIdx.x * 256 + threadIdx.x;   // NROWS*32 float4 slots
    const int row = idx >> 5;
    const int c4  = idx & 31;

    float mh[NSPLIT], lh[NSPLIT];
    float M = NEGINF;
#pragma unroll
    for (int h = 0; h < NSPLIT; h++) {
        mh[h] = g_mpart[h * NROWS + row];
        lh[h] = g_lpart[h * NROWS + row];
        M = fmaxf(M, mh[h]);
    }
    float wsum = 0.f, wh[NSPLIT];
#pragma unroll
    for (int h = 0; h < NSPLIT; h++) {
        wh[h] = lh[h] * __expf(mh[h] - M);   // l=0 split -> weight 0
        wsum += wh[h];
    }
    const float inv = 1.0f / wsum;

    const size_t off = ((size_t)row << 7) + (c4 << 2);
    float4 r = make_float4(0.f, 0.f, 0.f, 0.f);
#pragma unroll
    for (int h = 0; h < NSPLIT; h++) {
        const float wn = wh[h] * inv;
        if (wn > 0.f) {
            const float4 a = *(const float4*)(g_opart + (size_t)h * NROWS * HD + off);
            r.x += wn * a.x; r.y += wn * a.y; r.z += wn * a.z; r.w += wn * a.w;
        }
    }
    *(float4*)(out + off) = r;
}

// ===========================================================================
extern "C" void kernel_launch(void* const* d_in, const int* in_sizes, int n_in,
                              void* d_out, int out_size)
{
    const float* x  = (const float*)d_in[0];
    const float* Wq = (const float*)d_in[1];
    const float* Wk = (const float*)d_in[2];
    const float* Wv = (const float*)d_in[3];
    float* out = (float*)d_out;

    cudaFuncSetAttribute(attn_kernel, cudaFuncAttributeMaxDynamicSharedMemorySize, ATT_SMEM);

    qkv_mma_kernel<<<dim3(NROWS / 128, 3), 256>>>(x, Wq, Wk, Wv);
    attn_kernel<<<dim3(S_LEN / 128, B_SZ, NSPLIT), 256, ATT_SMEM>>>();
    combine_kernel<<<(NROWS * 32) / 256, 256>>>(out);
}

// round 9
// speedup vs baseline: 4.6889x; 1.0134x over previous
#include <cuda_runtime.h>
#include <cstdint>
#include <math.h>

#define S_LEN 4096
#define B_SZ  2
#define HD    128
#define DM    4096
#define NROWS (B_SZ * S_LEN)
#define NEGINF (-1e30f)
#define NSPLIT 4

// scratch
__device__ float g_q[NROWS * HD];
__device__ float g_k[NROWS * HD];
__device__ float g_v[NROWS * HD];
__device__ float g_opart[NSPLIT * NROWS * HD];
__device__ float g_mpart[NSPLIT * NROWS];
__device__ float g_lpart[NSPLIT * NROWS];
__device__ uint32_t g_wt[3 * HD * DM];   // W pre-converted to tf32 bits

// ---------------- portable tensor-core helpers (sm_80+ PTX) ----------------
__device__ __forceinline__ uint32_t f2tf(float x) {
    uint32_t r;
    asm("cvt.rna.tf32.f32 %0, %1;" : "=r"(r) : "f"(x));
    return r;
}
// D(16x8,f32) += A(16x8,tf32) * B(8x8,tf32)
__device__ __forceinline__ void mma8(float c[4], const uint32_t a[4], const uint32_t b[2]) {
    asm volatile(
        "mma.sync.aligned.m16n8k8.row.col.f32.tf32.tf32.f32 "
        "{%0,%1,%2,%3}, {%4,%5,%6,%7}, {%8,%9}, {%0,%1,%2,%3};"
        : "+f"(c[0]), "+f"(c[1]), "+f"(c[2]), "+f"(c[3])
        : "r"(a[0]), "r"(a[1]), "r"(a[2]), "r"(a[3]), "r"(b[0]), "r"(b[1]));
}
__device__ __forceinline__ uint32_t smem_u32(const void* p) {
    uint32_t a;
    asm("{ .reg .u64 t; cvta.to.shared.u64 t, %1; cvt.u32.u64 %0, t; }" : "=r"(a) : "l"(p));
    return a;
}
#define CP_ASYNC16(dst_u32, src_ptr) \
    asm volatile("cp.async.cg.shared.global [%0], [%1], 16;" \
                 :: "r"(dst_u32), "l"(src_ptr) : "memory")
#define CP_COMMIT()  asm volatile("cp.async.commit_group;" ::: "memory")
#define CP_WAIT(n)   asm volatile("cp.async.wait_group %0;" :: "n"(n) : "memory")

// ===========================================================================
// Kernel A0: one-time W -> tf32 conversion (3 x 128 x 4096 elements)
// ===========================================================================
__global__ __launch_bounds__(256) void wconv_kernel(
    const float* __restrict__ Wq,
    const float* __restrict__ Wk,
    const float* __restrict__ Wv)
{
    const int idx = (blockIdx.x * 256 + threadIdx.x) * 4;   // over 3*HD*DM
    const int per = HD * DM;
    const int z   = idx / per;
    const float* src = (z == 0) ? Wq : (z == 1) ? Wk : Wv;
    const float4 v = *(const float4*)(src + (idx - z * per));
    *(uint4*)(g_wt + idx) = make_uint4(f2tf(v.x), f2tf(v.y), f2tf(v.z), f2tf(v.w));
}

// ===========================================================================
// Kernel A: QKV projection C[8192,128] = X[8192,4096] * W^T via tf32 mma,
// fused RoPE epilogue. BM=128, BN=128, BK=32, warp grid 4(m) x 2(n).
// 3-stage cp.async pipeline: X staged as raw fp32 (cvt at A-frag load),
// W staged pre-converted from g_wt. One __syncthreads per chunk.
// ===========================================================================
#define PJW 36      // smem row stride in words
#define STG 3
#define STAGE_W (128 * PJW)                    // words per array per stage
#define PROJ_SMEM (STG * 2 * STAGE_W * 4)      // 110592 bytes

__global__ __launch_bounds__(256) void qkv_mma_kernel(
    const float* __restrict__ x,
    const float* __restrict__ Wq,
    const float* __restrict__ Wk,
    const float* __restrict__ Wv)
{
    extern __shared__ uint32_t smq[];
    uint32_t* Xs = smq;                        // [STG][128][PJW] raw fp32 bits
    uint32_t* Ws = smq + STG * STAGE_W;        // [STG][128][PJW] tf32 bits

    const int t    = threadIdx.x;
    const int lane = t & 31;
    const int w    = t >> 5;
    const int g    = lane >> 2;
    const int tg   = lane & 3;
    const int wm   = w & 3;       // m-warp: rows wm*32..+31
    const int wn   = w >> 2;      // n-warp: cols wn*64..+63
    const int z    = blockIdx.y;
    const int m0   = blockIdx.x * 128;
    float* __restrict__ dst = (z == 0) ? g_q : (z == 1) ? g_k : g_v;
    const uint32_t* __restrict__ wt = g_wt + (size_t)z * HD * DM;

    // per-thread copy map: 4 items covering 128 rows x 8 float4-segs
    int rowL[4], segL[4];
    uint32_t sby[4];                           // smem byte offset within a stage
#pragma unroll
    for (int i = 0; i < 4; i++) {
        int idx = i * 256 + t;
        rowL[i] = idx >> 3;
        segL[i] = idx & 7;
        sby[i]  = (uint32_t)(rowL[i] * PJW + segL[i] * 4) * 4;
    }
    const uint32_t sxs = smem_u32(Xs);
    const uint32_t sws = smem_u32(Ws);

    float acc[16][4];
#pragma unroll
    for (int n = 0; n < 16; n++)
#pragma unroll
        for (int j = 0; j < 4; j++) acc[n][j] = 0.f;

    const uint32_t am0 = (wm * 32 + g) * PJW;
    const uint32_t am1 = (wm * 32 + 16 + g) * PJW;
    const uint32_t bn0 = (wn * 64 + g) * PJW;

#define ISSUE(c, s) do { \
    const int _kb = (c) * 32; \
    const uint32_t _xd = sxs + (s) * (STAGE_W * 4); \
    const uint32_t _wd = sws + (s) * (STAGE_W * 4); \
    _Pragma("unroll") \
    for (int _i = 0; _i < 4; _i++) { \
        CP_ASYNC16(_xd + sby[_i], x  + (size_t)(m0 + rowL[_i]) * DM + _kb + segL[_i] * 4); \
        CP_ASYNC16(_wd + sby[_i], wt + (size_t)rowL[_i] * DM + _kb + segL[_i] * 4); \
    } \
    CP_COMMIT(); \
} while (0)

    ISSUE(0, 0);
    ISSUE(1, 1);

    const int NCH = DM / 32;   // 128
    for (int c = 0; c < NCH; c++) {
        if (c == NCH - 1) { CP_WAIT(0); } else { CP_WAIT(1); }
        __syncthreads();
        if (c + 2 < NCH) ISSUE(c + 2, (c + 2) % STG);

        const uint32_t* XsS = Xs + (c % STG) * STAGE_W;
        const uint32_t* WsS = Ws + (c % STG) * STAGE_W;
#pragma unroll
        for (int k8 = 0; k8 < 4; k8++) {
            const int ko = k8 * 8 + tg;
            uint32_t a0[4], a1[4];
            a0[0] = f2tf(__uint_as_float(XsS[am0 + ko]));
            a0[1] = f2tf(__uint_as_float(XsS[am0 + 8 * PJW + ko]));
            a0[2] = f2tf(__uint_as_float(XsS[am0 + ko + 4]));
            a0[3] = f2tf(__uint_as_float(XsS[am0 + 8 * PJW + ko + 4]));
            a1[0] = f2tf(__uint_as_float(XsS[am1 + ko]));
            a1[1] = f2tf(__uint_as_float(XsS[am1 + 8 * PJW + ko]));
            a1[2] = f2tf(__uint_as_float(XsS[am1 + ko + 4]));
            a1[3] = f2tf(__uint_as_float(XsS[am1 + 8 * PJW + ko + 4]));
#pragma unroll
            for (int n8 = 0; n8 < 8; n8++) {
                uint32_t bb[2];
                const uint32_t* wp = &WsS[bn0 + n8 * 8 * PJW + ko];
                bb[0] = wp[0];
                bb[1] = wp[4];
                mma8(acc[n8],     a0, bb);
                mma8(acc[8 + n8], a1, bb);
            }
        }
    }
#undef ISSUE

    // epilogue: RoPE (pairs are exactly cols 2p,2p+1) + store
#pragma unroll
    for (int mf = 0; mf < 2; mf++) {
        const int r0 = m0 + wm * 32 + mf * 16 + g;
        const int r1 = r0 + 8;
        if (z < 2) {
            const float s0 = (float)(r0 & (S_LEN - 1));
            const float s1 = (float)(r1 & (S_LEN - 1));
#pragma unroll
            for (int n8 = 0; n8 < 8; n8++) {
                float* a = acc[mf * 8 + n8];
                const int p = wn * 32 + n8 * 4 + tg;
                const float th = exp2f(-0.4152410118609203f * (float)p);
                float sn0, cs0, sn1, cs1;
                sincosf(s0 * th, &sn0, &cs0);
                sincosf(s1 * th, &sn1, &cs1);
                float a0 = a[0], a1 = a[1];
                a[0] = a0 * cs0 - a1 * sn0;
                a[1] = a1 * cs0 + a0 * sn0;
                float a2 = a[2], a3 = a[3];
                a[2] = a2 * cs1 - a3 * sn1;
                a[3] = a3 * cs1 + a2 * sn1;
            }
        }
#pragma unroll
        for (int n8 = 0; n8 < 8; n8++) {
            const float* a = acc[mf * 8 + n8];
            const int c = wn * 64 + n8 * 8 + 2 * tg;
            *(float2*)(dst + (size_t)r0 * HD + c) = make_float2(a[0], a[1]);
            *(float2*)(dst + (size_t)r1 * HD + c) = make_float2(a[2], a[3]);
        }
    }
}

// ===========================================================================
// Kernel B: causal flash attention, tf32 mma, register softmax.
// CTA = 128 queries (8 warps x m16); 4-way KV split (blockIdx.z).
// ===========================================================================
#define KS_STR  72    // Ks [d:128][key:64], %32==8
#define VS_STR2 136   // Vs [key:64][hd:128], %32==8
#define PS_STR  72    // Ps per-warp [row:16][key:64], %32==8
#define ATT_SMEM ((128 * KS_STR + 64 * VS_STR2 + 8 * 16 * PS_STR) * 4)

__global__ __launch_bounds__(256) void attn_kernel()
{
    extern __shared__ uint32_t sm[];
    uint32_t* Ks = sm;                       // tf32 K^T tile
    uint32_t* Vs = Ks + 128 * KS_STR;        // tf32 V tile
    uint32_t* Ps = Vs + 64 * VS_STR2;        // tf32 P, per-warp slices

    const int t    = threadIdx.x;
    const int lane = t & 31;
    const int w    = t >> 5;
    const int g    = lane >> 2;
    const int tg   = lane & 3;
    const int b    = blockIdx.y;
    const int h    = blockIdx.z;
    const int qt   = (S_LEN / 128 - 1) - blockIdx.x;   // heavy CTAs first

    const int gr0 = qt * 128 + w * 16 + g;
    const int gr1 = gr0 + 8;
    const int statbase = h * NROWS + b * S_LEN;

    // split [0, ntiles) into NSPLIT chunks
    const int ntiles = 2 * qt + 2;
    const int cs = (ntiles + NSPLIT - 1) / NSPLIT;
    const int j0 = h * cs;
    const int j1 = min(ntiles, j0 + cs);
    if (j0 >= j1) {      // empty split: stats only (weight 0 in combine)
        if (tg == 0) {
            g_mpart[statbase + gr0] = NEGINF; g_lpart[statbase + gr0] = 0.f;
            g_mpart[statbase + gr1] = NEGINF; g_lpart[statbase + gr1] = 0.f;
        }
        return;
    }

    const float* __restrict__ qb = g_q + (size_t)b * S_LEN * HD;
    const float* __restrict__ kb = g_k + (size_t)b * S_LEN * HD;
    const float* __restrict__ vb = g_v + (size_t)b * S_LEN * HD;

    const float SCALE = 0.08838834764831845f;  // 1/sqrt(128)

    // Q fragments (scale folded in), held in registers for the whole CTA
    uint32_t qf[16][4];
#pragma unroll
    for (int k8 = 0; k8 < 16; k8++) {
        const float* p0 = qb + (size_t)gr0 * HD + k8 * 8;
        const float* p1 = qb + (size_t)gr1 * HD + k8 * 8;
        qf[k8][0] = f2tf(p0[tg] * SCALE);
        qf[k8][1] = f2tf(p1[tg] * SCALE);
        qf[k8][2] = f2tf(p0[tg + 4] * SCALE);
        qf[k8][3] = f2tf(p1[tg + 4] * SCALE);
    }

    float of[16][4];
#pragma unroll
    for (int n = 0; n < 16; n++)
#pragma unroll
        for (int j = 0; j < 4; j++) of[n][j] = 0.f;
    float m0 = NEGINF, m1 = NEGINF, l0 = 0.f, l1 = 0.f;

    uint32_t* pw = &Ps[w * 16 * PS_STR];

    for (int jt = j0; jt < j1; jt++) {
        __syncthreads();
        // load K (transposed, tf32) and V (tf32) tiles
#pragma unroll
        for (int i = 0; i < 8; i++) {
            int idx = i * 256 + t;
            int key = idx & 63, seg = idx >> 6;   // seg 0..31 (float4 of d)
            float4 kv = *(const float4*)(kb + (size_t)(jt * 64 + key) * HD + seg * 4);
            Ks[(seg * 4 + 0) * KS_STR + key] = f2tf(kv.x);
            Ks[(seg * 4 + 1) * KS_STR + key] = f2tf(kv.y);
            Ks[(seg * 4 + 2) * KS_STR + key] = f2tf(kv.z);
            Ks[(seg * 4 + 3) * KS_STR + key] = f2tf(kv.w);
            float4 vv = *(const float4*)(vb + (size_t)(jt * 64 + key) * HD + seg * 4);
            uint32_t* vp = &Vs[key * VS_STR2 + seg * 4];
            vp[0] = f2tf(vv.x); vp[1] = f2tf(vv.y); vp[2] = f2tf(vv.z); vp[3] = f2tf(vv.w);
        }
        __syncthreads();

        // S = (Q*scale) K^T
        float sf[8][4];
#pragma unroll
        for (int n = 0; n < 8; n++)
#pragma unroll
            for (int j = 0; j < 4; j++) sf[n][j] = 0.f;
#pragma unroll
        for (int k8 = 0; k8 < 16; k8++) {
#pragma unroll
            for (int n8 = 0; n8 < 8; n8++) {
                uint32_t bb[2];
                const uint32_t* kp = &Ks[(k8 * 8 + tg) * KS_STR + n8 * 8 + g];
                bb[0] = kp[0];
                bb[1] = kp[4 * KS_STR];
                mma8(sf[n8], qf[k8], bb);
            }
        }

        // causal mask (only tiles that straddle the diagonal)
        if (jt >= 2 * qt) {
#pragma unroll
            for (int n8 = 0; n8 < 8; n8++) {
                const int c0 = jt * 64 + n8 * 8 + 2 * tg;
                const int c1 = c0 + 1;
                if (c0 > gr0) sf[n8][0] = NEGINF;
                if (c1 > gr0) sf[n8][1] = NEGINF;
                if (c0 > gr1) sf[n8][2] = NEGINF;
                if (c1 > gr1) sf[n8][3] = NEGINF;
            }
        }

        // row max (quad shuffle over the 4 threads holding the row)
        float mx0 = NEGINF, mx1 = NEGINF;
#pragma unroll
        for (int n8 = 0; n8 < 8; n8++) {
            mx0 = fmaxf(mx0, fmaxf(sf[n8][0], sf[n8][1]));
            mx1 = fmaxf(mx1, fmaxf(sf[n8][2], sf[n8][3]));
        }
        mx0 = fmaxf(mx0, __shfl_xor_sync(0xFFFFFFFFu, mx0, 1));
        mx0 = fmaxf(mx0, __shfl_xor_sync(0xFFFFFFFFu, mx0, 2));
        mx1 = fmaxf(mx1, __shfl_xor_sync(0xFFFFFFFFu, mx1, 1));
        mx1 = fmaxf(mx1, __shfl_xor_sync(0xFFFFFFFFu, mx1, 2));

        const float mn0 = fmaxf(m0, mx0);
        const float mn1 = fmaxf(m1, mx1);
        const float al0 = __expf(m0 - mn0);   // -1e30 sentinel -> exp underflows to 0
        const float al1 = __expf(m1 - mn1);

        // p = exp(s - m), sum
        float sum0 = 0.f, sum1 = 0.f;
#pragma unroll
        for (int n8 = 0; n8 < 8; n8++) {
            sf[n8][0] = __expf(sf[n8][0] - mn0);
            sf[n8][1] = __expf(sf[n8][1] - mn0);
            sf[n8][2] = __expf(sf[n8][2] - mn1);
            sf[n8][3] = __expf(sf[n8][3] - mn1);
            sum0 += sf[n8][0] + sf[n8][1];
            sum1 += sf[n8][2] + sf[n8][3];
        }
        sum0 += __shfl_xor_sync(0xFFFFFFFFu, sum0, 1);
        sum0 += __shfl_xor_sync(0xFFFFFFFFu, sum0, 2);
        sum1 += __shfl_xor_sync(0xFFFFFFFFu, sum1, 1);
        sum1 += __shfl_xor_sync(0xFFFFFFFFu, sum1, 2);
        l0 = l0 * al0 + sum0; m0 = mn0;
        l1 = l1 * al1 + sum1; m1 = mn1;

        // stage P into warp-private smem (C-layout write, A-layout read)
#pragma unroll
        for (int n8 = 0; n8 < 8; n8++) {
            uint2 pk0 = make_uint2(f2tf(sf[n8][0]), f2tf(sf[n8][1]));
            *(uint2*)&pw[g * PS_STR + n8 * 8 + 2 * tg] = pk0;
            uint2 pk1 = make_uint2(f2tf(sf[n8][2]), f2tf(sf[n8][3]));
            *(uint2*)&pw[(g + 8) * PS_STR + n8 * 8 + 2 * tg] = pk1;
        }
        __syncwarp();

        // rescale O
#pragma unroll
        for (int n8 = 0; n8 < 16; n8++) {
            of[n8][0] *= al0; of[n8][1] *= al0;
            of[n8][2] *= al1; of[n8][3] *= al1;
        }

        // O += P V
#pragma unroll
        for (int k8 = 0; k8 < 8; k8++) {
            uint32_t af[4];
            af[0] = pw[g * PS_STR + k8 * 8 + tg];
            af[1] = pw[(g + 8) * PS_STR + k8 * 8 + tg];
            af[2] = pw[g * PS_STR + k8 * 8 + tg + 4];
            af[3] = pw[(g + 8) * PS_STR + k8 * 8 + tg + 4];
#pragma unroll
            for (int n8 = 0; n8 < 16; n8++) {
                uint32_t bb[2];
                const uint32_t* vp = &Vs[(k8 * 8 + tg) * VS_STR2 + n8 * 8 + g];
                bb[0] = vp[0];
                bb[1] = vp[4 * VS_STR2];
                mma8(of[n8], af, bb);
            }
        }
    }

    // write partials (normalized by own l) + stats
    const float inv0 = (l0 > 0.f) ? 1.0f / l0 : 0.f;
    const float inv1 = (l1 > 0.f) ? 1.0f / l1 : 0.f;
    float* ob = g_opart + ((size_t)h * NROWS + (size_t)b * S_LEN) * HD;
#pragma unroll
    for (int n8 = 0; n8 < 16; n8++) {
        const int c = n8 * 8 + 2 * tg;
        *(float2*)(ob + (size_t)gr0 * HD + c) = make_float2(of[n8][0] * inv0, of[n8][1] * inv0);
        *(float2*)(ob + (size_t)gr1 * HD + c) = make_float2(of[n8][2] * inv1, of[n8][3] * inv1);
    }
    if (tg == 0) {
        g_mpart[statbase + gr0] = m0; g_lpart[statbase + gr0] = l0;
        g_mpart[statbase + gr1] = m1; g_lpart[statbase + gr1] = l1;
    }
}

// ===========================================================================
// Kernel C: combine the NSPLIT partial-softmax results.
// ===========================================================================
__global__ __launch_bounds__(256) void combine_kernel(float* __restrict__ out)
{
    const int idx = blockIdx.x * 256 + threadIdx.x;   // NROWS*32 float4 slots
    const int row = idx >> 5;
    const int c4  = idx & 31;

    float mh[NSPLIT], lh[NSPLIT];
    float M = NEGINF;
#pragma unroll
    for (int h = 0; h < NSPLIT; h++) {
        mh[h] = g_mpart[h * NROWS + row];
        lh[h] = g_lpart[h * NROWS + row];
        M = fmaxf(M, mh[h]);
    }
    float wsum = 0.f, wh[NSPLIT];
#pragma unroll
    for (int h = 0; h < NSPLIT; h++) {
        wh[h] = lh[h] * __expf(mh[h] - M);   // l=0 split -> weight 0
        wsum += wh[h];
    }
    const float inv = 1.0f / wsum;

    const size_t off = ((size_t)row << 7) + (c4 << 2);
    float4 r = make_float4(0.f, 0.f, 0.f, 0.f);
#pragma unroll
    for (int h = 0; h < NSPLIT; h++) {
        const float wn = wh[h] * inv;
        if (wn > 0.f) {
            const float4 a = *(const float4*)(g_opart + (size_t)h * NROWS * HD + off);
            r.x += wn * a.x; r.y += wn * a.y; r.z += wn * a.z; r.w += wn * a.w;
        }
    }
    *(float4*)(out + off) = r;
}

// ===========================================================================
extern "C" void kernel_launch(void* const* d_in, const int* in_sizes, int n_in,
                              void* d_out, int out_size)
{
    const float* x  = (const float*)d_in[0];
    const float* Wq = (const float*)d_in[1];
    const float* Wk = (const float*)d_in[2];
    const float* Wv = (const float*)d_in[3];
    float* out = (float*)d_out;

    cudaFuncSetAttribute(qkv_mma_kernel, cudaFuncAttributeMaxDynamicSharedMemorySize, PROJ_SMEM);
    cudaFuncSetAttribute(attn_kernel,    cudaFuncAttributeMaxDynamicSharedMemorySize, ATT_SMEM);

    wconv_kernel<<<(3 * HD * DM / 4) / 256, 256>>>(Wq, Wk, Wv);
    qkv_mma_kernel<<<dim3(NROWS / 128, 3), 256, PROJ_SMEM>>>(x, Wq, Wk, Wv);
    attn_kernel<<<dim3(S_LEN / 128, B_SZ, NSPLIT), 256, ATT_SMEM>>>();
    combine_kernel<<<(NROWS * 32) / 256, 256>>>(out);
}

// round 10
// speedup vs baseline: 6.4830x; 1.3826x over previous
#include <cuda_runtime.h>
#include <cuda_fp16.h>
#include <cstdint>
#include <math.h>

#define S_LEN 4096
#define B_SZ  2
#define HD    128
#define DM    4096
#define NROWS (B_SZ * S_LEN)
#define NEGINF (-1e30f)
#define NSPLIT 4

// scratch
__device__ float g_q[NROWS * HD];
__device__ float g_k[NROWS * HD];
__device__ float g_v[NROWS * HD];
__device__ float g_opart[NSPLIT * NROWS * HD];
__device__ float g_mpart[NSPLIT * NROWS];
__device__ float g_lpart[NSPLIT * NROWS];
__device__ uint32_t g_wt[3 * HD * DM / 2];   // W packed f16x2: word j = (k=2j lo, 2j+1 hi)

// ---------------- helpers ----------------
__device__ __forceinline__ uint32_t h2(float lo, float hi) {
    uint32_t r;
    asm("cvt.rn.f16x2.f32 %0, %1, %2;" : "=r"(r) : "f"(hi), "f"(lo));
    return r;
}
// D(16x8,f32) += A(16x16,f16) * B(16x8,f16)
__device__ __forceinline__ void mma16(float c[4], const uint32_t a[4], const uint32_t b[2]) {
    asm volatile(
        "mma.sync.aligned.m16n8k16.row.col.f32.f16.f16.f32 "
        "{%0,%1,%2,%3}, {%4,%5,%6,%7}, {%8,%9}, {%0,%1,%2,%3};"
        : "+f"(c[0]), "+f"(c[1]), "+f"(c[2]), "+f"(c[3])
        : "r"(a[0]), "r"(a[1]), "r"(a[2]), "r"(a[3]), "r"(b[0]), "r"(b[1]));
}
__device__ __forceinline__ uint32_t smem_u32(const void* p) {
    uint32_t a;
    asm("{ .reg .u64 t; cvta.to.shared.u64 t, %1; cvt.u32.u64 %0, t; }" : "=r"(a) : "l"(p));
    return a;
}
#define CP_ASYNC16(dst_u32, src_ptr) \
    asm volatile("cp.async.cg.shared.global [%0], [%1], 16;" \
                 :: "r"(dst_u32), "l"(src_ptr) : "memory")
#define CP_COMMIT()  asm volatile("cp.async.commit_group;" ::: "memory")
#define CP_WAIT(n)   asm volatile("cp.async.wait_group %0;" :: "n"(n) : "memory")

// ===========================================================================
// Kernel A0: one-time W -> packed fp16 conversion
// ===========================================================================
__global__ __launch_bounds__(256) void wconv_kernel(
    const float* __restrict__ Wq,
    const float* __restrict__ Wk,
    const float* __restrict__ Wv)
{
    const int gid = blockIdx.x * 256 + threadIdx.x;
    const int f   = gid * 4;                   // over 3*HD*DM floats
    const int per = HD * DM;
    const int z   = f / per;
    const float* src = (z == 0) ? Wq : (z == 1) ? Wk : Wv;
    const float4 v = *(const float4*)(src + (f - z * per));
    *(uint2*)(g_wt + f / 2) = make_uint2(h2(v.x, v.y), h2(v.z, v.w));
}

// ===========================================================================
// Kernel A: QKV projection via fp16 mma (m16n8k16), fused RoPE epilogue.
// BM=128, BN=128, BK=32, warp grid 4(m) x 2(n), 3-stage cp.async pipeline.
// X staged raw fp32 (cvt at A-frag load); W staged packed fp16.
// ===========================================================================
#define PJW 36                 // X row stride (fp32 words)
#define WJW 20                 // W row stride (f16x2 words); 20 % 32 -> conflict-free B reads
#define STG 3
#define XSTAGE (128 * PJW)     // words
#define WSTAGE (128 * WJW)     // words
#define PROJ_SMEM (STG * (XSTAGE + WSTAGE) * 4)   // 86016 B

__global__ __launch_bounds__(256, 2) void qkv_mma_kernel(const float* __restrict__ x)
{
    extern __shared__ uint32_t smq[];
    uint32_t* Xs = smq;                        // [STG][128][PJW] raw fp32 bits
    uint32_t* Ws = smq + STG * XSTAGE;         // [STG][128][WJW] f16x2

    const int t    = threadIdx.x;
    const int lane = t & 31;
    const int w    = t >> 5;
    const int g    = lane >> 2;
    const int tg   = lane & 3;
    const int wm   = w & 3;       // m-warp: rows wm*32..+31
    const int wn   = w >> 2;      // n-warp: cols wn*64..+63
    const int z    = blockIdx.y;
    const int m0   = blockIdx.x * 128;
    float* __restrict__ dst = (z == 0) ? g_q : (z == 1) ? g_k : g_v;
    const uint32_t* __restrict__ wt = g_wt + (size_t)z * (HD * DM / 2);

    // X copy map: 4 items covering 128 rows x 8 float4-segs
    int rowL[4], segL[4];
    uint32_t sbyX[4];
#pragma unroll
    for (int i = 0; i < 4; i++) {
        int idx = i * 256 + t;
        rowL[i] = idx >> 3;
        segL[i] = idx & 7;
        sbyX[i] = (uint32_t)(rowL[i] * PJW + segL[i] * 4) * 4;
    }
    // W copy map: 2 items covering 128 rows x 4 word-segs (4 words each)
    int wrowL[2], wsegL[2];
    uint32_t sbyW[2];
#pragma unroll
    for (int i = 0; i < 2; i++) {
        int idx = i * 256 + t;
        wrowL[i] = idx >> 2;
        wsegL[i] = idx & 3;
        sbyW[i]  = (uint32_t)(wrowL[i] * WJW + wsegL[i] * 4) * 4;
    }
    const uint32_t sxs = smem_u32(Xs);
    const uint32_t sws = smem_u32(Ws);

    float acc[16][4];
#pragma unroll
    for (int n = 0; n < 16; n++)
#pragma unroll
        for (int j = 0; j < 4; j++) acc[n][j] = 0.f;

    const uint32_t am0  = (wm * 32 + g) * PJW;        // m-frag 0 row g
    const uint32_t am1  = (wm * 32 + 16 + g) * PJW;   // m-frag 1
    const uint32_t bn0w = (wn * 64 + g) * WJW;

#define ISSUE(c, s) do { \
    const int _kb = (c) * 32; \
    const uint32_t _xd = sxs + (s) * (XSTAGE * 4); \
    const uint32_t _wd = sws + (s) * (WSTAGE * 4); \
    _Pragma("unroll") \
    for (int _i = 0; _i < 4; _i++) \
        CP_ASYNC16(_xd + sbyX[_i], x + (size_t)(m0 + rowL[_i]) * DM + _kb + segL[_i] * 4); \
    _Pragma("unroll") \
    for (int _i = 0; _i < 2; _i++) \
        CP_ASYNC16(_wd + sbyW[_i], wt + (size_t)wrowL[_i] * (DM / 2) + (c) * 16 + wsegL[_i] * 4); \
    CP_COMMIT(); \
} while (0)

    ISSUE(0, 0);
    ISSUE(1, 1);

    const int NCH = DM / 32;   // 128
    for (int c = 0; c < NCH; c++) {
        if (c == NCH - 1) { CP_WAIT(0); } else { CP_WAIT(1); }
        __syncthreads();
        if (c + 2 < NCH) ISSUE(c + 2, (c + 2) % STG);

        const float*    Xf  = (const float*)(Xs + (c % STG) * XSTAGE);
        const uint32_t* WsS = Ws + (c % STG) * WSTAGE;
#pragma unroll
        for (int s = 0; s < 2; s++) {           // two k16 steps per BK=32 chunk
            const int kb = s * 16 + 2 * tg;
            float2 p00 = *(const float2*)&Xf[am0 + kb];
            float2 p01 = *(const float2*)&Xf[am0 + kb + 8];
            float2 p02 = *(const float2*)&Xf[am0 + 8 * PJW + kb];
            float2 p03 = *(const float2*)&Xf[am0 + 8 * PJW + kb + 8];
            uint32_t a0[4] = { h2(p00.x, p00.y), h2(p02.x, p02.y),
                               h2(p01.x, p01.y), h2(p03.x, p03.y) };
            float2 p10 = *(const float2*)&Xf[am1 + kb];
            float2 p11 = *(const float2*)&Xf[am1 + kb + 8];
            float2 p12 = *(const float2*)&Xf[am1 + 8 * PJW + kb];
            float2 p13 = *(const float2*)&Xf[am1 + 8 * PJW + kb + 8];
            uint32_t a1[4] = { h2(p10.x, p10.y), h2(p12.x, p12.y),
                               h2(p11.x, p11.y), h2(p13.x, p13.y) };
#pragma unroll
            for (int n8 = 0; n8 < 8; n8++) {
                const uint32_t* wp = &WsS[bn0w + n8 * 8 * WJW + s * 8 + tg];
                uint32_t bb[2] = { wp[0], wp[4] };
                mma16(acc[n8],     a0, bb);
                mma16(acc[8 + n8], a1, bb);
            }
        }
    }
#undef ISSUE

    // epilogue: RoPE (pairs are exactly cols 2p,2p+1) + store
#pragma unroll
    for (int mf = 0; mf < 2; mf++) {
        const int r0 = m0 + wm * 32 + mf * 16 + g;
        const int r1 = r0 + 8;
        if (z < 2) {
            const float s0 = (float)(r0 & (S_LEN - 1));
            const float s1 = (float)(r1 & (S_LEN - 1));
#pragma unroll
            for (int n8 = 0; n8 < 8; n8++) {
                float* a = acc[mf * 8 + n8];
                const int p = wn * 32 + n8 * 4 + tg;
                const float th = exp2f(-0.4152410118609203f * (float)p);
                float sn0, cs0, sn1, cs1;
                sincosf(s0 * th, &sn0, &cs0);
                sincosf(s1 * th, &sn1, &cs1);
                float a0 = a[0], a1 = a[1];
                a[0] = a0 * cs0 - a1 * sn0;
                a[1] = a1 * cs0 + a0 * sn0;
                float a2 = a[2], a3 = a[3];
                a[2] = a2 * cs1 - a3 * sn1;
                a[3] = a3 * cs1 + a2 * sn1;
            }
        }
#pragma unroll
        for (int n8 = 0; n8 < 8; n8++) {
            const float* a = acc[mf * 8 + n8];
            const int c = wn * 64 + n8 * 8 + 2 * tg;
            *(float2*)(dst + (size_t)r0 * HD + c) = make_float2(a[0], a[1]);
            *(float2*)(dst + (size_t)r1 * HD + c) = make_float2(a[2], a[3]);
        }
    }
}

// ===========================================================================
// Kernel B: causal flash attention, fp16 mma, register softmax.
// CTA = 128 queries (8 warps x m16); 4-way KV split (blockIdx.z).
// K: [key][d-pair f16x2] stride 68; V: [hd][key-pair f16x2] stride 36;
// P: per-warp [row][key-pair f16x2] stride 36.
// ===========================================================================
#define KP_STR 68
#define VP_STR 36
#define PP_STR 36
#define ATT_SMEM ((64 * KP_STR + 128 * VP_STR + 8 * 16 * PP_STR) * 4)

__global__ __launch_bounds__(256) void attn_kernel()
{
    extern __shared__ uint32_t sm[];
    uint32_t* Kp = sm;                        // f16x2 K
    uint32_t* Vp = Kp + 64 * KP_STR;          // f16x2 V
    uint32_t* Ps = Vp + 128 * VP_STR;         // f16x2 P, per-warp slices

    const int t    = threadIdx.x;
    const int lane = t & 31;
    const int w    = t >> 5;
    const int g    = lane >> 2;
    const int tg   = lane & 3;
    const int b    = blockIdx.y;
    const int h    = blockIdx.z;
    const int qt   = (S_LEN / 128 - 1) - blockIdx.x;   // heavy CTAs first

    const int gr0 = qt * 128 + w * 16 + g;
    const int gr1 = gr0 + 8;
    const int statbase = h * NROWS + b * S_LEN;

    const int ntiles = 2 * qt + 2;
    const int cs = (ntiles + NSPLIT - 1) / NSPLIT;
    const int j0 = h * cs;
    const int j1 = min(ntiles, j0 + cs);
    if (j0 >= j1) {      // empty split: stats only (weight 0 in combine)
        if (tg == 0) {
            g_mpart[statbase + gr0] = NEGINF; g_lpart[statbase + gr0] = 0.f;
            g_mpart[statbase + gr1] = NEGINF; g_lpart[statbase + gr1] = 0.f;
        }
        return;
    }

    const float* __restrict__ qb = g_q + (size_t)b * S_LEN * HD;
    const float* __restrict__ kb = g_k + (size_t)b * S_LEN * HD;
    const float* __restrict__ vb = g_v + (size_t)b * S_LEN * HD;

    const float SCALE = 0.08838834764831845f;  // 1/sqrt(128)

    // Q fragments (fp16, scale folded in): 8 k16-steps x 4 regs
    uint32_t qf[8][4];
#pragma unroll
    for (int s = 0; s < 8; s++) {
        const int kb2 = s * 16 + 2 * tg;
        float2 q00 = *(const float2*)(qb + (size_t)gr0 * HD + kb2);
        float2 q01 = *(const float2*)(qb + (size_t)gr0 * HD + kb2 + 8);
        float2 q10 = *(const float2*)(qb + (size_t)gr1 * HD + kb2);
        float2 q11 = *(const float2*)(qb + (size_t)gr1 * HD + kb2 + 8);
        qf[s][0] = h2(q00.x * SCALE, q00.y * SCALE);
        qf[s][1] = h2(q10.x * SCALE, q10.y * SCALE);
        qf[s][2] = h2(q01.x * SCALE, q01.y * SCALE);
        qf[s][3] = h2(q11.x * SCALE, q11.y * SCALE);
    }

    float of[16][4];
#pragma unroll
    for (int n = 0; n < 16; n++)
#pragma unroll
        for (int j = 0; j < 4; j++) of[n][j] = 0.f;
    float m0 = NEGINF, m1 = NEGINF, l0 = 0.f, l1 = 0.f;

    uint32_t* pw = &Ps[w * 16 * PP_STR];
    __half* vh = (__half*)Vp;

    for (int jt = j0; jt < j1; jt++) {
        __syncthreads();
        // load K (packed d-pairs) and V (packed key-pairs, 16-bit scatter)
#pragma unroll
        for (int i = 0; i < 8; i++) {
            int idx = i * 256 + t;
            int key = idx & 63, seg = idx >> 6;   // seg 0..31 (float4 of d)
            float4 kv = *(const float4*)(kb + (size_t)(jt * 64 + key) * HD + seg * 4);
            *(uint2*)&Kp[key * KP_STR + seg * 2] =
                make_uint2(h2(kv.x, kv.y), h2(kv.z, kv.w));
            float4 vv = *(const float4*)(vb + (size_t)(jt * 64 + key) * HD + seg * 4);
            vh[(seg * 4 + 0) * (2 * VP_STR) + key] = __float2half(vv.x);
            vh[(seg * 4 + 1) * (2 * VP_STR) + key] = __float2half(vv.y);
            vh[(seg * 4 + 2) * (2 * VP_STR) + key] = __float2half(vv.z);
            vh[(seg * 4 + 3) * (2 * VP_STR) + key] = __float2half(vv.w);
        }
        __syncthreads();

        // S = (Q*scale) K^T
        float sf[8][4];
#pragma unroll
        for (int n = 0; n < 8; n++)
#pragma unroll
            for (int j = 0; j < 4; j++) sf[n][j] = 0.f;
#pragma unroll
        for (int s = 0; s < 8; s++) {
#pragma unroll
            for (int n8 = 0; n8 < 8; n8++) {
                const uint32_t* kp = &Kp[(n8 * 8 + g) * KP_STR + s * 8 + tg];
                uint32_t bb[2] = { kp[0], kp[4] };
                mma16(sf[n8], qf[s], bb);
            }
        }

        // causal mask (only tiles that straddle the diagonal)
        if (jt >= 2 * qt) {
#pragma unroll
            for (int n8 = 0; n8 < 8; n8++) {
                const int c0 = jt * 64 + n8 * 8 + 2 * tg;
                const int c1 = c0 + 1;
                if (c0 > gr0) sf[n8][0] = NEGINF;
                if (c1 > gr0) sf[n8][1] = NEGINF;
                if (c0 > gr1) sf[n8][2] = NEGINF;
                if (c1 > gr1) sf[n8][3] = NEGINF;
            }
        }

        // row max
        float mx0 = NEGINF, mx1 = NEGINF;
#pragma unroll
        for (int n8 = 0; n8 < 8; n8++) {
            mx0 = fmaxf(mx0, fmaxf(sf[n8][0], sf[n8][1]));
            mx1 = fmaxf(mx1, fmaxf(sf[n8][2], sf[n8][3]));
        }
        mx0 = fmaxf(mx0, __shfl_xor_sync(0xFFFFFFFFu, mx0, 1));
        mx0 = fmaxf(mx0, __shfl_xor_sync(0xFFFFFFFFu, mx0, 2));
        mx1 = fmaxf(mx1, __shfl_xor_sync(0xFFFFFFFFu, mx1, 1));
        mx1 = fmaxf(mx1, __shfl_xor_sync(0xFFFFFFFFu, mx1, 2));

        const float mn0 = fmaxf(m0, mx0);
        const float mn1 = fmaxf(m1, mx1);
        const float al0 = __expf(m0 - mn0);
        const float al1 = __expf(m1 - mn1);

        float sum0 = 0.f, sum1 = 0.f;
#pragma unroll
        for (int n8 = 0; n8 < 8; n8++) {
            sf[n8][0] = __expf(sf[n8][0] - mn0);
            sf[n8][1] = __expf(sf[n8][1] - mn0);
            sf[n8][2] = __expf(sf[n8][2] - mn1);
            sf[n8][3] = __expf(sf[n8][3] - mn1);
            sum0 += sf[n8][0] + sf[n8][1];
            sum1 += sf[n8][2] + sf[n8][3];
        }
        sum0 += __shfl_xor_sync(0xFFFFFFFFu, sum0, 1);
        sum0 += __shfl_xor_sync(0xFFFFFFFFu, sum0, 2);
        sum1 += __shfl_xor_sync(0xFFFFFFFFu, sum1, 1);
        sum1 += __shfl_xor_sync(0xFFFFFFFFu, sum1, 2);
        l0 = l0 * al0 + sum0; m0 = mn0;
        l1 = l1 * al1 + sum1; m1 = mn1;

        // stage P as packed f16x2 key-pairs (C pair (c0,c1) IS a key pair)
#pragma unroll
        for (int n8 = 0; n8 < 8; n8++) {
            pw[g * PP_STR + n8 * 4 + tg]       = h2(sf[n8][0], sf[n8][1]);
            pw[(g + 8) * PP_STR + n8 * 4 + tg] = h2(sf[n8][2], sf[n8][3]);
        }
        __syncwarp();

        // rescale O
#pragma unroll
        for (int n8 = 0; n8 < 16; n8++) {
            of[n8][0] *= al0; of[n8][1] *= al0;
            of[n8][2] *= al1; of[n8][3] *= al1;
        }

        // O += P V  (4 k16 steps over 64 keys)
#pragma unroll
        for (int s = 0; s < 4; s++) {
            uint32_t af[4];
            af[0] = pw[g * PP_STR + s * 8 + tg];
            af[1] = pw[(g + 8) * PP_STR + s * 8 + tg];
            af[2] = pw[g * PP_STR + s * 8 + tg + 4];
            af[3] = pw[(g + 8) * PP_STR + s * 8 + tg + 4];
#pragma unroll
            for (int n8 = 0; n8 < 16; n8++) {
                const uint32_t* vp = &Vp[(n8 * 8 + g) * VP_STR + s * 8 + tg];
                uint32_t bb[2] = { vp[0], vp[4] };
                mma16(of[n8], af, bb);
            }
        }
    }

    // write partials (normalized by own l) + stats
    const float inv0 = (l0 > 0.f) ? 1.0f / l0 : 0.f;
    const float inv1 = (l1 > 0.f) ? 1.0f / l1 : 0.f;
    float* ob = g_opart + ((size_t)h * NROWS + (size_t)b * S_LEN) * HD;
#pragma unroll
    for (int n8 = 0; n8 < 16; n8++) {
        const int c = n8 * 8 + 2 * tg;
        *(float2*)(ob + (size_t)gr0 * HD + c) = make_float2(of[n8][0] * inv0, of[n8][1] * inv0);
        *(float2*)(ob + (size_t)gr1 * HD + c) = make_float2(of[n8][2] * inv1, of[n8][3] * inv1);
    }
    if (tg == 0) {
        g_mpart[statbase + gr0] = m0; g_lpart[statbase + gr0] = l0;
        g_mpart[statbase + gr1] = m1; g_lpart[statbase + gr1] = l1;
    }
}

// ===========================================================================
// Kernel C: combine the NSPLIT partial-softmax results.
// ===========================================================================
__global__ __launch_bounds__(256) void combine_kernel(float* __restrict__ out)
{
    const int idx = blockIdx.x * 256 + threadIdx.x;   // NROWS*32 float4 slots
    const int row = idx >> 5;
    const int c4  = idx & 31;

    float mh[NSPLIT], lh[NSPLIT];
    float M = NEGINF;
#pragma unroll
    for (int h = 0; h < NSPLIT; h++) {
        mh[h] = g_mpart[h * NROWS + row];
        lh[h] = g_lpart[h * NROWS + row];
        M = fmaxf(M, mh[h]);
    }
    float wsum = 0.f, wh[NSPLIT];
#pragma unroll
    for (int h = 0; h < NSPLIT; h++) {
        wh[h] = lh[h] * __expf(mh[h] - M);   // l=0 split -> weight 0
        wsum += wh[h];
    }
    const float inv = 1.0f / wsum;

    const size_t off = ((size_t)row << 7) + (c4 << 2);
    float4 r = make_float4(0.f, 0.f, 0.f, 0.f);
#pragma unroll
    for (int h = 0; h < NSPLIT; h++) {
        const float wn = wh[h] * inv;
        if (wn > 0.f) {
            const float4 a = *(const float4*)(g_opart + (size_t)h * NROWS * HD + off);
            r.x += wn * a.x; r.y += wn * a.y; r.z += wn * a.z; r.w += wn * a.w;
        }
    }
    *(float4*)(out + off) = r;
}

// ===========================================================================
extern "C" void kernel_launch(void* const* d_in, const int* in_sizes, int n_in,
                              void* d_out, int out_size)
{
    const float* x  = (const float*)d_in[0];
    const float* Wq = (const float*)d_in[1];
    const float* Wk = (const float*)d_in[2];
    const float* Wv = (const float*)d_in[3];
    float* out = (float*)d_out;

    cudaFuncSetAttribute(qkv_mma_kernel, cudaFuncAttributeMaxDynamicSharedMemorySize, PROJ_SMEM);
    cudaFuncSetAttribute(attn_kernel,    cudaFuncAttributeMaxDynamicSharedMemorySize, ATT_SMEM);

    wconv_kernel<<<(3 * HD * DM / 4) / 256, 256>>>(Wq, Wk, Wv);
    qkv_mma_kernel<<<dim3(NROWS / 128, 3), 256, PROJ_SMEM>>>(x);
    attn_kernel<<<dim3(S_LEN / 128, B_SZ, NSPLIT), 256, ATT_SMEM>>>();
    combine_kernel<<<(NROWS * 32) / 256, 256>>>(out);
}

// round 11
// speedup vs baseline: 7.6883x; 1.1859x over previous
#include <cuda_runtime.h>
#include <cuda_fp16.h>
#include <cstdint>
#include <math.h>

#define S_LEN 4096
#define B_SZ  2
#define HD    128
#define DM    4096
#define NROWS (B_SZ * S_LEN)
#define NEGINF (-1e30f)
#define NSPLIT 4

// scratch (fp16 packed words)
__device__ uint32_t g_qh[NROWS * HD / 2];     // [row][d-pair], SCALE folded
__device__ uint32_t g_kh[NROWS * HD / 2];     // [row][d-pair]
__device__ uint32_t g_vt[HD * NROWS / 2];     // [d][global-row-pair]
__device__ uint32_t g_wt[3 * HD * DM / 2];    // W packed f16x2
__device__ float g_opart[NSPLIT * NROWS * HD];
__device__ float g_mpart[NSPLIT * NROWS];
__device__ float g_lpart[NSPLIT * NROWS];

// ---------------- helpers ----------------
__device__ __forceinline__ uint32_t h2(float lo, float hi) {
    uint32_t r;
    asm("cvt.rn.f16x2.f32 %0, %1, %2;" : "=r"(r) : "f"(hi), "f"(lo));
    return r;
}
// D(16x8,f32) += A(16x16,f16) * B(16x8,f16)
__device__ __forceinline__ void mma16(float c[4], const uint32_t a[4], const uint32_t b[2]) {
    asm volatile(
        "mma.sync.aligned.m16n8k16.row.col.f32.f16.f16.f32 "
        "{%0,%1,%2,%3}, {%4,%5,%6,%7}, {%8,%9}, {%0,%1,%2,%3};"
        : "+f"(c[0]), "+f"(c[1]), "+f"(c[2]), "+f"(c[3])
        : "r"(a[0]), "r"(a[1]), "r"(a[2]), "r"(a[3]), "r"(b[0]), "r"(b[1]));
}
__device__ __forceinline__ uint32_t smem_u32(const void* p) {
    uint32_t a;
    asm("{ .reg .u64 t; cvta.to.shared.u64 t, %1; cvt.u32.u64 %0, t; }" : "=r"(a) : "l"(p));
    return a;
}
#define CP_ASYNC16(dst_u32, src_ptr) \
    asm volatile("cp.async.cg.shared.global [%0], [%1], 16;" \
                 :: "r"(dst_u32), "l"(src_ptr) : "memory")
#define CP_COMMIT()  asm volatile("cp.async.commit_group;" ::: "memory")
#define CP_WAIT(n)   asm volatile("cp.async.wait_group %0;" :: "n"(n) : "memory")

// ===========================================================================
// Kernel A0: one-time W -> packed fp16
// ===========================================================================
__global__ __launch_bounds__(256) void wconv_kernel(
    const float* __restrict__ Wq,
    const float* __restrict__ Wk,
    const float* __restrict__ Wv)
{
    const int f   = (blockIdx.x * 256 + threadIdx.x) * 4;
    const int per = HD * DM;
    const int z   = f / per;
    const float* src = (z == 0) ? Wq : (z == 1) ? Wk : Wv;
    const float4 v = *(const float4*)(src + (f - z * per));
    *(uint2*)(g_wt + f / 2) = make_uint2(h2(v.x, v.y), h2(v.z, v.w));
}

// ===========================================================================
// Kernel A: QKV projection via fp16 mma, fused RoPE; outputs packed fp16.
// z=0: q (RoPE, SCALE folded) -> g_qh;  z=1: k (RoPE) -> g_kh;
// z=2: v transposed through smem -> g_vt[d][row-pair].
// ===========================================================================
#define PJW 36
#define WJW 20
#define STG 3
#define XSTAGE (128 * PJW)
#define WSTAGE (128 * WJW)
#define PROJ_SMEM (STG * (XSTAGE + WSTAGE) * 4)   // 86016 B

__global__ __launch_bounds__(256, 2) void qkv_mma_kernel(const float* __restrict__ x)
{
    extern __shared__ uint32_t smq[];
    uint32_t* Xs = smq;
    uint32_t* Ws = smq + STG * XSTAGE;

    const int t    = threadIdx.x;
    const int lane = t & 31;
    const int w    = t >> 5;
    const int g    = lane >> 2;
    const int tg   = lane & 3;
    const int wm   = w & 3;
    const int wn   = w >> 2;
    const int z    = blockIdx.y;
    const int m0   = blockIdx.x * 128;
    const uint32_t* __restrict__ wt = g_wt + (size_t)z * (HD * DM / 2);

    int rowL[4], segL[4];
    uint32_t sbyX[4];
#pragma unroll
    for (int i = 0; i < 4; i++) {
        int idx = i * 256 + t;
        rowL[i] = idx >> 3;
        segL[i] = idx & 7;
        sbyX[i] = (uint32_t)(rowL[i] * PJW + segL[i] * 4) * 4;
    }
    int wrowL[2], wsegL[2];
    uint32_t sbyW[2];
#pragma unroll
    for (int i = 0; i < 2; i++) {
        int idx = i * 256 + t;
        wrowL[i] = idx >> 2;
        wsegL[i] = idx & 3;
        sbyW[i]  = (uint32_t)(wrowL[i] * WJW + wsegL[i] * 4) * 4;
    }
    const uint32_t sxs = smem_u32(Xs);
    const uint32_t sws = smem_u32(Ws);

    float acc[16][4];
#pragma unroll
    for (int n = 0; n < 16; n++)
#pragma unroll
        for (int j = 0; j < 4; j++) acc[n][j] = 0.f;

    const uint32_t am0  = (wm * 32 + g) * PJW;
    const uint32_t am1  = (wm * 32 + 16 + g) * PJW;
    const uint32_t bn0w = (wn * 64 + g) * WJW;

#define ISSUE(c, s) do { \
    const int _kb = (c) * 32; \
    const uint32_t _xd = sxs + (s) * (XSTAGE * 4); \
    const uint32_t _wd = sws + (s) * (WSTAGE * 4); \
    _Pragma("unroll") \
    for (int _i = 0; _i < 4; _i++) \
        CP_ASYNC16(_xd + sbyX[_i], x + (size_t)(m0 + rowL[_i]) * DM + _kb + segL[_i] * 4); \
    _Pragma("unroll") \
    for (int _i = 0; _i < 2; _i++) \
        CP_ASYNC16(_wd + sbyW[_i], wt + (size_t)wrowL[_i] * (DM / 2) + (c) * 16 + wsegL[_i] * 4); \
    CP_COMMIT(); \
} while (0)

    ISSUE(0, 0);
    ISSUE(1, 1);

    const int NCH = DM / 32;
    for (int c = 0; c < NCH; c++) {
        if (c == NCH - 1) { CP_WAIT(0); } else { CP_WAIT(1); }
        __syncthreads();
        if (c + 2 < NCH) ISSUE(c + 2, (c + 2) % STG);

        const float*    Xf  = (const float*)(Xs + (c % STG) * XSTAGE);
        const uint32_t* WsS = Ws + (c % STG) * WSTAGE;
#pragma unroll
        for (int s = 0; s < 2; s++) {
            const int kb = s * 16 + 2 * tg;
            float2 p00 = *(const float2*)&Xf[am0 + kb];
            float2 p01 = *(const float2*)&Xf[am0 + kb + 8];
            float2 p02 = *(const float2*)&Xf[am0 + 8 * PJW + kb];
            float2 p03 = *(const float2*)&Xf[am0 + 8 * PJW + kb + 8];
            uint32_t a0[4] = { h2(p00.x, p00.y), h2(p02.x, p02.y),
                               h2(p01.x, p01.y), h2(p03.x, p03.y) };
            float2 p10 = *(const float2*)&Xf[am1 + kb];
            float2 p11 = *(const float2*)&Xf[am1 + kb + 8];
            float2 p12 = *(const float2*)&Xf[am1 + 8 * PJW + kb];
            float2 p13 = *(const float2*)&Xf[am1 + 8 * PJW + kb + 8];
            uint32_t a1[4] = { h2(p10.x, p10.y), h2(p12.x, p12.y),
                               h2(p11.x, p11.y), h2(p13.x, p13.y) };
#pragma unroll
            for (int n8 = 0; n8 < 8; n8++) {
                const uint32_t* wp = &WsS[bn0w + n8 * 8 * WJW + s * 8 + tg];
                uint32_t bb[2] = { wp[0], wp[4] };
                mma16(acc[n8],     a0, bb);
                mma16(acc[8 + n8], a1, bb);
            }
        }
    }
#undef ISSUE

    const float SCALE = 0.08838834764831845f;   // 1/sqrt(128)

    if (z < 2) {
        uint32_t* dsth = (z == 0) ? g_qh : g_kh;
        const float fs = (z == 0) ? SCALE : 1.0f;
#pragma unroll
        for (int mf = 0; mf < 2; mf++) {
            const int r0 = m0 + wm * 32 + mf * 16 + g;
            const int r1 = r0 + 8;
            const float s0 = (float)(r0 & (S_LEN - 1));
            const float s1 = (float)(r1 & (S_LEN - 1));
#pragma unroll
            for (int n8 = 0; n8 < 8; n8++) {
                float* a = acc[mf * 8 + n8];
                const int p = wn * 32 + n8 * 4 + tg;
                const float th = exp2f(-0.4152410118609203f * (float)p);
                float sn0, cs0, sn1, cs1;
                sincosf(s0 * th, &sn0, &cs0);
                sincosf(s1 * th, &sn1, &cs1);
                const float b0 = (a[0] * cs0 - a[1] * sn0) * fs;
                const float b1 = (a[1] * cs0 + a[0] * sn0) * fs;
                const float b2 = (a[2] * cs1 - a[3] * sn1) * fs;
                const float b3 = (a[3] * cs1 + a[2] * sn1) * fs;
                dsth[(size_t)r0 * 64 + p] = h2(b0, b1);
                dsth[(size_t)r1 * 64 + p] = h2(b2, b3);
            }
        }
    } else {
        // V: transpose through smem -> g_vt[d][row-pair]
        __syncthreads();
        __half* vts = (__half*)smq;                  // [col 128][row 128], stride 132
#pragma unroll
        for (int mf = 0; mf < 2; mf++) {
            const int rl0 = wm * 32 + mf * 16 + g;   // local rows
            const int rl1 = rl0 + 8;
#pragma unroll
            for (int n8 = 0; n8 < 8; n8++) {
                const float* a = acc[mf * 8 + n8];
                const int c = wn * 64 + n8 * 8 + 2 * tg;
                vts[c * 132 + rl0]       = __float2half(a[0]);
                vts[(c + 1) * 132 + rl0] = __float2half(a[1]);
                vts[c * 132 + rl1]       = __float2half(a[2]);
                vts[(c + 1) * 132 + rl1] = __float2half(a[3]);
            }
        }
        __syncthreads();
        const int d  = t >> 1;
        const int p0 = (t & 1) * 32;
#pragma unroll
        for (int i = 0; i < 32; i++) {
            const uint32_t wv = *(const uint32_t*)&vts[d * 132 + (p0 + i) * 2];
            g_vt[(size_t)d * (NROWS / 2) + (m0 >> 1) + p0 + i] = wv;
        }
    }
}

// ===========================================================================
// Kernel B: causal flash attention, fp16 mma, cp.async K/V double buffer.
// K stage [key][d-pair] stride 68; V stage [hd][key-pair] stride 36.
// ===========================================================================
#define KSTGW (64 * 68)               // 4352 words
#define VSTGW (128 * 36)              // 4608 words
#define STGW  (KSTGW + VSTGW)         // 8960 words per stage
#define PP_STR 36
#define ATT_SMEM ((2 * STGW + 8 * 16 * PP_STR) * 4)   // 90112 B

__global__ __launch_bounds__(256) void attn_kernel()
{
    extern __shared__ uint32_t sma[];
    uint32_t* Ps = sma + 2 * STGW;

    const int t    = threadIdx.x;
    const int lane = t & 31;
    const int w    = t >> 5;
    const int g    = lane >> 2;
    const int tg   = lane & 3;
    const int b    = blockIdx.y;
    const int h    = blockIdx.z;
    const int qt   = (S_LEN / 128 - 1) - blockIdx.x;

    const int gr0 = qt * 128 + w * 16 + g;
    const int gr1 = gr0 + 8;
    const int statbase = h * NROWS + b * S_LEN;

    const int ntiles = 2 * qt + 2;
    const int cs = (ntiles + NSPLIT - 1) / NSPLIT;
    const int j0 = h * cs;
    const int j1 = min(ntiles, j0 + cs);
    if (j0 >= j1) {
        if (tg == 0) {
            g_mpart[statbase + gr0] = NEGINF; g_lpart[statbase + gr0] = 0.f;
            g_mpart[statbase + gr1] = NEGINF; g_lpart[statbase + gr1] = 0.f;
        }
        return;
    }

    // copy maps: K 1024 chunks (64 keys x 16), V 1024 chunks (128 d x 8)
    int kkey[4], kseg[4], vd[4], vseg[4];
#pragma unroll
    for (int i = 0; i < 4; i++) {
        int idx = i * 256 + t;
        kkey[i] = idx >> 4; kseg[i] = idx & 15;
        vd[i]   = idx >> 3; vseg[i] = idx & 7;
    }
    const uint32_t sbase = smem_u32(sma);

#define AISSUE(jt, s) do { \
    const size_t _brow = (size_t)b * S_LEN + (size_t)(jt) * 64; \
    const uint32_t _kd = sbase + (s) * (STGW * 4); \
    const uint32_t _vd = _kd + KSTGW * 4; \
    _Pragma("unroll") \
    for (int _i = 0; _i < 4; _i++) { \
        CP_ASYNC16(_kd + kkey[_i] * 272 + kseg[_i] * 16, \
                   g_kh + (_brow + kkey[_i]) * 64 + kseg[_i] * 4); \
        CP_ASYNC16(_vd + vd[_i] * 144 + vseg[_i] * 16, \
                   g_vt + (size_t)vd[_i] * (NROWS / 2) + (_brow >> 1) + vseg[_i] * 4); \
    } \
    CP_COMMIT(); \
} while (0)

    // Q fragments (pre-scaled fp16 in gmem): direct word loads
    const uint32_t* qw = g_qh + (size_t)b * S_LEN * 64;
    uint32_t qf[8][4];
#pragma unroll
    for (int s = 0; s < 8; s++) {
        qf[s][0] = qw[(size_t)gr0 * 64 + s * 8 + tg];
        qf[s][1] = qw[(size_t)gr1 * 64 + s * 8 + tg];
        qf[s][2] = qw[(size_t)gr0 * 64 + s * 8 + tg + 4];
        qf[s][3] = qw[(size_t)gr1 * 64 + s * 8 + tg + 4];
    }

    float of[16][4];
#pragma unroll
    for (int n = 0; n < 16; n++)
#pragma unroll
        for (int j = 0; j < 4; j++) of[n][j] = 0.f;
    float m0 = NEGINF, m1 = NEGINF, l0 = 0.f, l1 = 0.f;

    uint32_t* pw = &Ps[w * 16 * PP_STR];

    AISSUE(j0, 0);

    for (int jt = j0; jt < j1; jt++) {
        const int buf = (jt - j0) & 1;
        CP_WAIT(0);
        __syncthreads();
        if (jt + 1 < j1) AISSUE(jt + 1, buf ^ 1);

        const uint32_t* Kp = sma + buf * STGW;
        const uint32_t* Vp = Kp + KSTGW;

        // S = Q K^T
        float sf[8][4];
#pragma unroll
        for (int n = 0; n < 8; n++)
#pragma unroll
            for (int j = 0; j < 4; j++) sf[n][j] = 0.f;
#pragma unroll
        for (int s = 0; s < 8; s++) {
#pragma unroll
            for (int n8 = 0; n8 < 8; n8++) {
                const uint32_t* kp = &Kp[(n8 * 8 + g) * 68 + s * 8 + tg];
                uint32_t bb[2] = { kp[0], kp[4] };
                mma16(sf[n8], qf[s], bb);
            }
        }

        // causal mask
        if (jt >= 2 * qt) {
#pragma unroll
            for (int n8 = 0; n8 < 8; n8++) {
                const int c0 = jt * 64 + n8 * 8 + 2 * tg;
                const int c1 = c0 + 1;
                if (c0 > gr0) sf[n8][0] = NEGINF;
                if (c1 > gr0) sf[n8][1] = NEGINF;
                if (c0 > gr1) sf[n8][2] = NEGINF;
                if (c1 > gr1) sf[n8][3] = NEGINF;
            }
        }

        // online softmax
        float mx0 = NEGINF, mx1 = NEGINF;
#pragma unroll
        for (int n8 = 0; n8 < 8; n8++) {
            mx0 = fmaxf(mx0, fmaxf(sf[n8][0], sf[n8][1]));
            mx1 = fmaxf(mx1, fmaxf(sf[n8][2], sf[n8][3]));
        }
        mx0 = fmaxf(mx0, __shfl_xor_sync(0xFFFFFFFFu, mx0, 1));
        mx0 = fmaxf(mx0, __shfl_xor_sync(0xFFFFFFFFu, mx0, 2));
        mx1 = fmaxf(mx1, __shfl_xor_sync(0xFFFFFFFFu, mx1, 1));
        mx1 = fmaxf(mx1, __shfl_xor_sync(0xFFFFFFFFu, mx1, 2));

        const float mn0 = fmaxf(m0, mx0);
        const float mn1 = fmaxf(m1, mx1);
        const float al0 = __expf(m0 - mn0);
        const float al1 = __expf(m1 - mn1);

        float sum0 = 0.f, sum1 = 0.f;
#pragma unroll
        for (int n8 = 0; n8 < 8; n8++) {
            sf[n8][0] = __expf(sf[n8][0] - mn0);
            sf[n8][1] = __expf(sf[n8][1] - mn0);
            sf[n8][2] = __expf(sf[n8][2] - mn1);
            sf[n8][3] = __expf(sf[n8][3] - mn1);
            sum0 += sf[n8][0] + sf[n8][1];
            sum1 += sf[n8][2] + sf[n8][3];
        }
        sum0 += __shfl_xor_sync(0xFFFFFFFFu, sum0, 1);
        sum0 += __shfl_xor_sync(0xFFFFFFFFu, sum0, 2);
        sum1 += __shfl_xor_sync(0xFFFFFFFFu, sum1, 1);
        sum1 += __shfl_xor_sync(0xFFFFFFFFu, sum1, 2);
        l0 = l0 * al0 + sum0; m0 = mn0;
        l1 = l1 * al1 + sum1; m1 = mn1;

        // stage P as f16x2 key-pairs
#pragma unroll
        for (int n8 = 0; n8 < 8; n8++) {
            pw[g * PP_STR + n8 * 4 + tg]       = h2(sf[n8][0], sf[n8][1]);
            pw[(g + 8) * PP_STR + n8 * 4 + tg] = h2(sf[n8][2], sf[n8][3]);
        }
        __syncwarp();

#pragma unroll
        for (int n8 = 0; n8 < 16; n8++) {
            of[n8][0] *= al0; of[n8][1] *= al0;
            of[n8][2] *= al1; of[n8][3] *= al1;
        }

        // O += P V
#pragma unroll
        for (int s = 0; s < 4; s++) {
            uint32_t af[4];
            af[0] = pw[g * PP_STR + s * 8 + tg];
            af[1] = pw[(g + 8) * PP_STR + s * 8 + tg];
            af[2] = pw[g * PP_STR + s * 8 + tg + 4];
            af[3] = pw[(g + 8) * PP_STR + s * 8 + tg + 4];
#pragma unroll
            for (int n8 = 0; n8 < 16; n8++) {
                const uint32_t* vp = &Vp[(n8 * 8 + g) * 36 + s * 8 + tg];
                uint32_t bb[2] = { vp[0], vp[4] };
                mma16(of[n8], af, bb);
            }
        }
    }
#undef AISSUE

    const float inv0 = (l0 > 0.f) ? 1.0f / l0 : 0.f;
    const float inv1 = (l1 > 0.f) ? 1.0f / l1 : 0.f;
    float* ob = g_opart + ((size_t)h * NROWS + (size_t)b * S_LEN) * HD;
#pragma unroll
    for (int n8 = 0; n8 < 16; n8++) {
        const int c = n8 * 8 + 2 * tg;
        *(float2*)(ob + (size_t)gr0 * HD + c) = make_float2(of[n8][0] * inv0, of[n8][1] * inv0);
        *(float2*)(ob + (size_t)gr1 * HD + c) = make_float2(of[n8][2] * inv1, of[n8][3] * inv1);
    }
    if (tg == 0) {
        g_mpart[statbase + gr0] = m0; g_lpart[statbase + gr0] = l0;
        g_mpart[statbase + gr1] = m1; g_lpart[statbase + gr1] = l1;
    }
}

// ===========================================================================
// Kernel C: combine the NSPLIT partial-softmax results.
// ===========================================================================
__global__ __launch_bounds__(256) void combine_kernel(float* __restrict__ out)
{
    const int idx = blockIdx.x * 256 + threadIdx.x;
    const int row = idx >> 5;
    const int c4  = idx & 31;

    float mh[NSPLIT], lh[NSPLIT];
    float M = NEGINF;
#pragma unroll
    for (int h = 0; h < NSPLIT; h++) {
        mh[h] = g_mpart[h * NROWS + row];
        lh[h] = g_lpart[h * NROWS + row];
        M = fmaxf(M, mh[h]);
    }
    float wsum = 0.f, wh[NSPLIT];
#pragma unroll
    for (int h = 0; h < NSPLIT; h++) {
        wh[h] = lh[h] * __expf(mh[h] - M);
        wsum += wh[h];
    }
    const float inv = 1.0f / wsum;

    const size_t off = ((size_t)row << 7) + (c4 << 2);
    float4 r = make_float4(0.f, 0.f, 0.f, 0.f);
#pragma unroll
    for (int h = 0; h < NSPLIT; h++) {
        const float wn = wh[h] * inv;
        if (wn > 0.f) {
            const float4 a = *(const float4*)(g_opart + (size_t)h * NROWS * HD + off);
            r.x += wn * a.x; r.y += wn * a.y; r.z += wn * a.z; r.w += wn * a.w;
        }
    }
    *(float4*)(out + off) = r;
}

// ===========================================================================
extern "C" void kernel_launch(void* const* d_in, const int* in_sizes, int n_in,
                              void* d_out, int out_size)
{
    const float* x  = (const float*)d_in[0];
    const float* Wq = (const float*)d_in[1];
    const float* Wk = (const float*)d_in[2];
    const float* Wv = (const float*)d_in[3];
    float* out = (float*)d_out;

    cudaFuncSetAttribute(qkv_mma_kernel, cudaFuncAttributeMaxDynamicSharedMemorySize, PROJ_SMEM);
    cudaFuncSetAttribute(attn_kernel,    cudaFuncAttributeMaxDynamicSharedMemorySize, ATT_SMEM);

    wconv_kernel<<<(3 * HD * DM / 4) / 256, 256>>>(Wq, Wk, Wv);
    qkv_mma_kernel<<<dim3(NROWS / 128, 3), 256, PROJ_SMEM>>>(x);
    attn_kernel<<<dim3(S_LEN / 128, B_SZ, NSPLIT), 256, ATT_SMEM>>>();
    combine_kernel<<<(NROWS * 32) / 256, 256>>>(out);
}

// round 12
// speedup vs baseline: 9.4947x; 1.2349x over previous
#include <cuda_runtime.h>
#include <cuda_fp16.h>
#include <cstdint>
#include <math.h>

#define S_LEN 4096
#define B_SZ  2
#define HD    128
#define DM    4096
#define NROWS (B_SZ * S_LEN)
#define NEGINF (-1e30f)
#define NSPLIT 4

// scratch
__device__ uint32_t g_qh[NROWS * HD / 2];     // [row][d-pair] f16x2, SCALE folded
__device__ uint32_t g_kh[NROWS * HD / 2];     // [row][d-pair] f16x2
__device__ uint32_t g_vt[HD * NROWS / 2];     // [d][global-row-pair] f16x2
__device__ uint32_t g_wt[3 * HD * DM / 2];    // W f16x2, fragment-interleaved groups
__device__ float    g_part[6 * NROWS * HD];   // qkv K-split partials [z*2+ks][row][col]
__device__ float g_opart[NSPLIT * NROWS * HD];
__device__ float g_mpart[NSPLIT * NROWS];
__device__ float g_lpart[NSPLIT * NROWS];

// ---------------- helpers ----------------
__device__ __forceinline__ uint32_t h2(float lo, float hi) {
    uint32_t r;
    asm("cvt.rn.f16x2.f32 %0, %1, %2;" : "=r"(r) : "f"(hi), "f"(lo));
    return r;
}
__device__ __forceinline__ void mma16(float c[4], const uint32_t a[4], const uint32_t b[2]) {
    asm volatile(
        "mma.sync.aligned.m16n8k16.row.col.f32.f16.f16.f32 "
        "{%0,%1,%2,%3}, {%4,%5,%6,%7}, {%8,%9}, {%0,%1,%2,%3};"
        : "+f"(c[0]), "+f"(c[1]), "+f"(c[2]), "+f"(c[3])
        : "r"(a[0]), "r"(a[1]), "r"(a[2]), "r"(a[3]), "r"(b[0]), "r"(b[1]));
}
__device__ __forceinline__ uint32_t smem_u32(const void* p) {
    uint32_t a;
    asm("{ .reg .u64 t; cvta.to.shared.u64 t, %1; cvt.u32.u64 %0, t; }" : "=r"(a) : "l"(p));
    return a;
}
#define CP_ASYNC16(dst_u32, src_ptr) \
    asm volatile("cp.async.cg.shared.global [%0], [%1], 16;" \
                 :: "r"(dst_u32), "l"(src_ptr) : "memory")
#define CP_COMMIT()  asm volatile("cp.async.commit_group;" ::: "memory")
#define CP_WAIT(n)   asm volatile("cp.async.wait_group %0;" :: "n"(n) : "memory")

// ===========================================================================
// Kernel A0: W -> fp16, fragment-interleaved: within each 8-word (16-float)
// group, position 2t' = orig word (t'), position 2t'+1 = orig word (t'+4).
// A warp thread tg then gets its B fragment (k-pair tg, k-pair tg+8) as one u64.
// ===========================================================================
__global__ __launch_bounds__(256) void wconv_kernel(
    const float* __restrict__ Wq,
    const float* __restrict__ Wk,
    const float* __restrict__ Wv)
{
    const int gid = blockIdx.x * 256 + threadIdx.x;   // 393216 threads
    const int wi  = gid * 2;                          // output word index
    const int z   = wi >> 18;                         // 262144 words per z
    const int r   = wi & 262143;
    const int n   = r >> 11;                          // 2048 words per row
    const int wr  = r & 2047;
    const int gs  = wr >> 3;
    const int tp  = (wr & 7) >> 1;
    const float* src = ((z == 0) ? Wq : (z == 1) ? Wk : Wv) + (size_t)n * DM + gs * 16 + 2 * tp;
    const float2 lo = *(const float2*)src;
    const float2 hi = *(const float2*)(src + 8);
    *(uint2*)(g_wt + wi) = make_uint2(h2(lo.x, lo.y), h2(hi.x, hi.y));
}

// ===========================================================================
// Kernel A: QKV projection, fp16 mma, K-split x2 -> fp32 partials.
// BM=128, BN=128, BK=32, warp grid 4(m) x 2(n), 3-stage cp.async.
// grid (64, 3, 2): blockIdx.z selects K half.
// ===========================================================================
#define PJW 40                 // X row stride (fp32 words), conflict-free f2 loads
#define WJW 24                 // W row stride (f16x2 words), conflict-free u64 loads
#define STG 3
#define XSTAGE (128 * PJW)
#define WSTAGE (128 * WJW)
#define PROJ_SMEM (STG * (XSTAGE + WSTAGE) * 4)   // 98304 B

__global__ __launch_bounds__(256, 2) void qkv_mma_kernel(const float* __restrict__ x)
{
    extern __shared__ uint32_t smq[];
    uint32_t* Xs = smq;
    uint32_t* Ws = smq + STG * XSTAGE;

    const int t    = threadIdx.x;
    const int lane = t & 31;
    const int w    = t >> 5;
    const int g    = lane >> 2;
    const int tg   = lane & 3;
    const int wm   = w & 3;
    const int wn   = w >> 2;
    const int z    = blockIdx.y;
    const int ks   = blockIdx.z;
    const int m0   = blockIdx.x * 128;
    const int K0   = ks * (DM / 2);
    const int K0w  = ks * (DM / 4);       // in f16x2 words
    const uint32_t* __restrict__ wt = g_wt + (size_t)z * (HD * DM / 2);

    int rowL[4], segL[4];
    uint32_t sbyX[4];
#pragma unroll
    for (int i = 0; i < 4; i++) {
        int idx = i * 256 + t;
        rowL[i] = idx >> 3;
        segL[i] = idx & 7;
        sbyX[i] = (uint32_t)(rowL[i] * PJW + segL[i] * 4) * 4;
    }
    int wrowL[2], wsegL[2];
    uint32_t sbyW[2];
#pragma unroll
    for (int i = 0; i < 2; i++) {
        int idx = i * 256 + t;
        wrowL[i] = idx >> 2;
        wsegL[i] = idx & 3;
        sbyW[i]  = (uint32_t)(wrowL[i] * WJW + wsegL[i] * 4) * 4;
    }
    const uint32_t sxs = smem_u32(Xs);
    const uint32_t sws = smem_u32(Ws);

    float acc[16][4];
#pragma unroll
    for (int n = 0; n < 16; n++)
#pragma unroll
        for (int j = 0; j < 4; j++) acc[n][j] = 0.f;

    const uint32_t am0  = (wm * 32 + g) * PJW;
    const uint32_t am1  = (wm * 32 + 16 + g) * PJW;
    const uint32_t bn0w = (wn * 64 + g) * WJW;

#define ISSUE(c, s) do { \
    const uint32_t _xd = sxs + (s) * (XSTAGE * 4); \
    const uint32_t _wd = sws + (s) * (WSTAGE * 4); \
    _Pragma("unroll") \
    for (int _i = 0; _i < 4; _i++) \
        CP_ASYNC16(_xd + sbyX[_i], x + (size_t)(m0 + rowL[_i]) * DM + K0 + (c) * 32 + segL[_i] * 4); \
    _Pragma("unroll") \
    for (int _i = 0; _i < 2; _i++) \
        CP_ASYNC16(_wd + sbyW[_i], wt + (size_t)wrowL[_i] * (DM / 2) + K0w + (c) * 16 + wsegL[_i] * 4); \
    CP_COMMIT(); \
} while (0)

    ISSUE(0, 0);
    ISSUE(1, 1);

    const int NCH = DM / 64;   // 64 chunks per K half
    for (int c = 0; c < NCH; c++) {
        if (c == NCH - 1) { CP_WAIT(0); } else { CP_WAIT(1); }
        __syncthreads();
        if (c + 2 < NCH) ISSUE(c + 2, (c + 2) % STG);

        const float*    Xf  = (const float*)(Xs + (c % STG) * XSTAGE);
        const uint32_t* WsS = Ws + (c % STG) * WSTAGE;
#pragma unroll
        for (int s = 0; s < 2; s++) {
            const int kb = s * 16 + 2 * tg;
            float2 p00 = *(const float2*)&Xf[am0 + kb];
            float2 p01 = *(const float2*)&Xf[am0 + kb + 8];
            float2 p02 = *(const float2*)&Xf[am0 + 8 * PJW + kb];
            float2 p03 = *(const float2*)&Xf[am0 + 8 * PJW + kb + 8];
            uint32_t a0[4] = { h2(p00.x, p00.y), h2(p02.x, p02.y),
                               h2(p01.x, p01.y), h2(p03.x, p03.y) };
            float2 p10 = *(const float2*)&Xf[am1 + kb];
            float2 p11 = *(const float2*)&Xf[am1 + kb + 8];
            float2 p12 = *(const float2*)&Xf[am1 + 8 * PJW + kb];
            float2 p13 = *(const float2*)&Xf[am1 + 8 * PJW + kb + 8];
            uint32_t a1[4] = { h2(p10.x, p10.y), h2(p12.x, p12.y),
                               h2(p11.x, p11.y), h2(p13.x, p13.y) };
#pragma unroll
            for (int n8 = 0; n8 < 8; n8++) {
                const uint2 ub = *(const uint2*)&WsS[bn0w + n8 * 8 * WJW + s * 8 + 2 * tg];
                uint32_t bb[2] = { ub.x, ub.y };
                mma16(acc[n8],     a0, bb);
                mma16(acc[8 + n8], a1, bb);
            }
        }
    }
#undef ISSUE

    // store raw fp32 partials
    float* dp = g_part + (size_t)(z * 2 + ks) * NROWS * HD;
#pragma unroll
    for (int mf = 0; mf < 2; mf++) {
        const int r0 = m0 + wm * 32 + mf * 16 + g;
        const int r1 = r0 + 8;
#pragma unroll
        for (int n8 = 0; n8 < 8; n8++) {
            const float* a = acc[mf * 8 + n8];
            const int c = wn * 64 + n8 * 8 + 2 * tg;
            *(float2*)(dp + (size_t)r0 * HD + c) = make_float2(a[0], a[1]);
            *(float2*)(dp + (size_t)r1 * HD + c) = make_float2(a[2], a[3]);
        }
    }
}

// ===========================================================================
// Kernel A2: reduce K-split partials; RoPE + fp16 pack (q,k); V transpose.
// grid (64, 3), 256 threads.
// ===========================================================================
__global__ __launch_bounds__(256) void qkv_reduce()
{
    __shared__ uint32_t st[128 * 68];   // z<2: [row][64 words +pad]; z=2: half[128][132]

    const int t    = threadIdx.x;
    const int z    = blockIdx.y;
    const int rblk = blockIdx.x * 128;
    const int rl   = t >> 1;
    const int hf   = t & 1;
    const int row  = rblk + rl;

    const float* p0 = g_part + (size_t)(2 * z)     * NROWS * HD + (size_t)row * HD;
    const float* p1 = g_part + (size_t)(2 * z + 1) * NROWS * HD + (size_t)row * HD;

    if (z < 2) {
        const float fs   = (z == 0) ? 0.08838834764831845f : 1.0f;
        const float srow = (float)(row & (S_LEN - 1));
#pragma unroll
        for (int i = 0; i < 32; i++) {
            const int p = hf * 32 + i;
            const float2 a0 = *(const float2*)(p0 + 2 * p);
            const float2 a1 = *(const float2*)(p1 + 2 * p);
            const float v0 = a0.x + a1.x;
            const float v1 = a0.y + a1.y;
            const float th = exp2f(-0.4152410118609203f * (float)p);
            float sn, cs;
            sincosf(srow * th, &sn, &cs);
            st[rl * 68 + p] = h2((v0 * cs - v1 * sn) * fs, (v1 * cs + v0 * sn) * fs);
        }
        __syncthreads();
        uint32_t* dsth = (z == 0) ? g_qh : g_kh;
#pragma unroll
        for (int j = 0; j < 32; j++) {
            const int idx = j * 256 + t;
            const int rr = idx >> 6, cc = idx & 63;
            dsth[(size_t)(rblk + rr) * 64 + cc] = st[rr * 68 + cc];
        }
    } else {
        __half* vh = (__half*)st;       // [d 128][row 132]
#pragma unroll
        for (int i = 0; i < 32; i++) {
            const int p = hf * 32 + i;
            const float2 a0 = *(const float2*)(p0 + 2 * p);
            const float2 a1 = *(const float2*)(p1 + 2 * p);
            vh[(2 * p)     * 132 + rl] = __float2half(a0.x + a1.x);
            vh[(2 * p + 1) * 132 + rl] = __float2half(a0.y + a1.y);
        }
        __syncthreads();
#pragma unroll
        for (int j = 0; j < 32; j++) {
            const int idx = j * 256 + t;
            const int d = idx >> 6, rp = idx & 63;
            g_vt[(size_t)d * (NROWS / 2) + (rblk >> 1) + rp] =
                *(const uint32_t*)&vh[d * 132 + rp * 2];
        }
    }
}

// ===========================================================================
// Kernel B: causal flash attention, fp16 mma, cp.async K/V double buffer.
// ===========================================================================
#define KSTGW (64 * 68)
#define VSTGW (128 * 36)
#define STGW  (KSTGW + VSTGW)
#define PP_STR 36
#define ATT_SMEM ((2 * STGW + 8 * 16 * PP_STR) * 4)   // 90112 B

__global__ __launch_bounds__(256) void attn_kernel()
{
    extern __shared__ uint32_t sma[];
    uint32_t* Ps = sma + 2 * STGW;

    const int t    = threadIdx.x;
    const int lane = t & 31;
    const int w    = t >> 5;
    const int g    = lane >> 2;
    const int tg   = lane & 3;
    const int b    = blockIdx.y;
    const int h    = blockIdx.z;
    const int qt   = (S_LEN / 128 - 1) - blockIdx.x;

    const int gr0 = qt * 128 + w * 16 + g;
    const int gr1 = gr0 + 8;
    const int statbase = h * NROWS + b * S_LEN;

    const int ntiles = 2 * qt + 2;
    const int cs = (ntiles + NSPLIT - 1) / NSPLIT;
    const int j0 = h * cs;
    const int j1 = min(ntiles, j0 + cs);
    if (j0 >= j1) {
        if (tg == 0) {
            g_mpart[statbase + gr0] = NEGINF; g_lpart[statbase + gr0] = 0.f;
            g_mpart[statbase + gr1] = NEGINF; g_lpart[statbase + gr1] = 0.f;
        }
        return;
    }

    int kkey[4], kseg[4], vd[4], vseg[4];
#pragma unroll
    for (int i = 0; i < 4; i++) {
        int idx = i * 256 + t;
        kkey[i] = idx >> 4; kseg[i] = idx & 15;
        vd[i]   = idx >> 3; vseg[i] = idx & 7;
    }
    const uint32_t sbase = smem_u32(sma);

#define AISSUE(jt, s) do { \
    const size_t _brow = (size_t)b * S_LEN + (size_t)(jt) * 64; \
    const uint32_t _kd = sbase + (s) * (STGW * 4); \
    const uint32_t _vd = _kd + KSTGW * 4; \
    _Pragma("unroll") \
    for (int _i = 0; _i < 4; _i++) { \
        CP_ASYNC16(_kd + kkey[_i] * 272 + kseg[_i] * 16, \
                   g_kh + (_brow + kkey[_i]) * 64 + kseg[_i] * 4); \
        CP_ASYNC16(_vd + vd[_i] * 144 + vseg[_i] * 16, \
                   g_vt + (size_t)vd[_i] * (NROWS / 2) + (_brow >> 1) + vseg[_i] * 4); \
    } \
    CP_COMMIT(); \
} while (0)

    const uint32_t* qw = g_qh + (size_t)b * S_LEN * 64;
    uint32_t qf[8][4];
#pragma unroll
    for (int s = 0; s < 8; s++) {
        qf[s][0] = qw[(size_t)gr0 * 64 + s * 8 + tg];
        qf[s][1] = qw[(size_t)gr1 * 64 + s * 8 + tg];
        qf[s][2] = qw[(size_t)gr0 * 64 + s * 8 + tg + 4];
        qf[s][3] = qw[(size_t)gr1 * 64 + s * 8 + tg + 4];
    }

    float of[16][4];
#pragma unroll
    for (int n = 0; n < 16; n++)
#pragma unroll
        for (int j = 0; j < 4; j++) of[n][j] = 0.f;
    float m0 = NEGINF, m1 = NEGINF, l0 = 0.f, l1 = 0.f;

    uint32_t* pw = &Ps[w * 16 * PP_STR];

    AISSUE(j0, 0);

    for (int jt = j0; jt < j1; jt++) {
        const int buf = (jt - j0) & 1;
        CP_WAIT(0);
        __syncthreads();
        if (jt + 1 < j1) AISSUE(jt + 1, buf ^ 1);

        const uint32_t* Kp = sma + buf * STGW;
        const uint32_t* Vp = Kp + KSTGW;

        float sf[8][4];
#pragma unroll
        for (int n = 0; n < 8; n++)
#pragma unroll
            for (int j = 0; j < 4; j++) sf[n][j] = 0.f;
#pragma unroll
        for (int s = 0; s < 8; s++) {
#pragma unroll
            for (int n8 = 0; n8 < 8; n8++) {
                const uint32_t* kp = &Kp[(n8 * 8 + g) * 68 + s * 8 + tg];
                uint32_t bb[2] = { kp[0], kp[4] };
                mma16(sf[n8], qf[s], bb);
            }
        }

        if (jt >= 2 * qt) {
#pragma unroll
            for (int n8 = 0; n8 < 8; n8++) {
                const int c0 = jt * 64 + n8 * 8 + 2 * tg;
                const int c1 = c0 + 1;
                if (c0 > gr0) sf[n8][0] = NEGINF;
                if (c1 > gr0) sf[n8][1] = NEGINF;
                if (c0 > gr1) sf[n8][2] = NEGINF;
                if (c1 > gr1) sf[n8][3] = NEGINF;
            }
        }

        float mx0 = NEGINF, mx1 = NEGINF;
#pragma unroll
        for (int n8 = 0; n8 < 8; n8++) {
            mx0 = fmaxf(mx0, fmaxf(sf[n8][0], sf[n8][1]));
            mx1 = fmaxf(mx1, fmaxf(sf[n8][2], sf[n8][3]));
        }
        mx0 = fmaxf(mx0, __shfl_xor_sync(0xFFFFFFFFu, mx0, 1));
        mx0 = fmaxf(mx0, __shfl_xor_sync(0xFFFFFFFFu, mx0, 2));
        mx1 = fmaxf(mx1, __shfl_xor_sync(0xFFFFFFFFu, mx1, 1));
        mx1 = fmaxf(mx1, __shfl_xor_sync(0xFFFFFFFFu, mx1, 2));

        const float mn0 = fmaxf(m0, mx0);
        const float mn1 = fmaxf(m1, mx1);
        const float al0 = __expf(m0 - mn0);
        const float al1 = __expf(m1 - mn1);

        float sum0 = 0.f, sum1 = 0.f;
#pragma unroll
        for (int n8 = 0; n8 < 8; n8++) {
            sf[n8][0] = __expf(sf[n8][0] - mn0);
            sf[n8][1] = __expf(sf[n8][1] - mn0);
            sf[n8][2] = __expf(sf[n8][2] - mn1);
            sf[n8][3] = __expf(sf[n8][3] - mn1);
            sum0 += sf[n8][0] + sf[n8][1];
            sum1 += sf[n8][2] + sf[n8][3];
        }
        sum0 += __shfl_xor_sync(0xFFFFFFFFu, sum0, 1);
        sum0 += __shfl_xor_sync(0xFFFFFFFFu, sum0, 2);
        sum1 += __shfl_xor_sync(0xFFFFFFFFu, sum1, 1);
        sum1 += __shfl_xor_sync(0xFFFFFFFFu, sum1, 2);
        l0 = l0 * al0 + sum0; m0 = mn0;
        l1 = l1 * al1 + sum1; m1 = mn1;

#pragma unroll
        for (int n8 = 0; n8 < 8; n8++) {
            pw[g * PP_STR + n8 * 4 + tg]       = h2(sf[n8][0], sf[n8][1]);
            pw[(g + 8) * PP_STR + n8 * 4 + tg] = h2(sf[n8][2], sf[n8][3]);
        }
        __syncwarp();

#pragma unroll
        for (int n8 = 0; n8 < 16; n8++) {
            of[n8][0] *= al0; of[n8][1] *= al0;
            of[n8][2] *= al1; of[n8][3] *= al1;
        }

#pragma unroll
        for (int s = 0; s < 4; s++) {
            uint32_t af[4];
            af[0] = pw[g * PP_STR + s * 8 + tg];
            af[1] = pw[(g + 8) * PP_STR + s * 8 + tg];
            af[2] = pw[g * PP_STR + s * 8 + tg + 4];
            af[3] = pw[(g + 8) * PP_STR + s * 8 + tg + 4];
#pragma unroll
            for (int n8 = 0; n8 < 16; n8++) {
                const uint32_t* vp = &Vp[(n8 * 8 + g) * 36 + s * 8 + tg];
                uint32_t bb[2] = { vp[0], vp[4] };
                mma16(of[n8], af, bb);
            }
        }
    }
#undef AISSUE

    const float inv0 = (l0 > 0.f) ? 1.0f / l0 : 0.f;
    const float inv1 = (l1 > 0.f) ? 1.0f / l1 : 0.f;
    float* ob = g_opart + ((size_t)h * NROWS + (size_t)b * S_LEN) * HD;
#pragma unroll
    for (int n8 = 0; n8 < 16; n8++) {
        const int c = n8 * 8 + 2 * tg;
        *(float2*)(ob + (size_t)gr0 * HD + c) = make_float2(of[n8][0] * inv0, of[n8][1] * inv0);
        *(float2*)(ob + (size_t)gr1 * HD + c) = make_float2(of[n8][2] * inv1, of[n8][3] * inv1);
    }
    if (tg == 0) {
        g_mpart[statbase + gr0] = m0; g_lpart[statbase + gr0] = l0;
        g_mpart[statbase + gr1] = m1; g_lpart[statbase + gr1] = l1;
    }
}

// ===========================================================================
// Kernel C: combine the NSPLIT partial-softmax results.
// ===========================================================================
__global__ __launch_bounds__(256) void combine_kernel(float* __restrict__ out)
{
    const int idx = blockIdx.x * 256 + threadIdx.x;
    const int row = idx >> 5;
    const int c4  = idx & 31;

    float mh[NSPLIT], lh[NSPLIT];
    float M = NEGINF;
#pragma unroll
    for (int h = 0; h < NSPLIT; h++) {
        mh[h] = g_mpart[h * NROWS + row];
        lh[h] = g_lpart[h * NROWS + row];
        M = fmaxf(M, mh[h]);
    }
    float wsum = 0.f, wh[NSPLIT];
#pragma unroll
    for (int h = 0; h < NSPLIT; h++) {
        wh[h] = lh[h] * __expf(mh[h] - M);
        wsum += wh[h];
    }
    const float inv = 1.0f / wsum;

    const size_t off = ((size_t)row << 7) + (c4 << 2);
    float4 r = make_float4(0.f, 0.f, 0.f, 0.f);
#pragma unroll
    for (int h = 0; h < NSPLIT; h++) {
        const float wn = wh[h] * inv;
        if (wn > 0.f) {
            const float4 a = *(const float4*)(g_opart + (size_t)h * NROWS * HD + off);
            r.x += wn * a.x; r.y += wn * a.y; r.z += wn * a.z; r.w += wn * a.w;
        }
    }
    *(float4*)(out + off) = r;
}

// ===========================================================================
extern "C" void kernel_launch(void* const* d_in, const int* in_sizes, int n_in,
                              void* d_out, int out_size)
{
    const float* x  = (const float*)d_in[0];
    const float* Wq = (const float*)d_in[1];
    const float* Wk = (const float*)d_in[2];
    const float* Wv = (const float*)d_in[3];
    float* out = (float*)d_out;

    cudaFuncSetAttribute(qkv_mma_kernel, cudaFuncAttributeMaxDynamicSharedMemorySize, PROJ_SMEM);
    cudaFuncSetAttribute(attn_kernel,    cudaFuncAttributeMaxDynamicSharedMemorySize, ATT_SMEM);

    wconv_kernel<<<1536, 256>>>(Wq, Wk, Wv);
    qkv_mma_kernel<<<dim3(NROWS / 128, 3, 2), 256, PROJ_SMEM>>>(x);
    qkv_reduce<<<dim3(NROWS / 128, 3), 256>>>();
    attn_kernel<<<dim3(S_LEN / 128, B_SZ, NSPLIT), 256, ATT_SMEM>>>();
    combine_kernel<<<(NROWS * 32) / 256, 256>>>(out);
}

// round 14
// speedup vs baseline: 9.9974x; 1.0530x over previous
#include <cuda_runtime.h>
#include <cuda_fp16.h>
#include <cstdint>
#include <math.h>

#define S_LEN 4096
#define B_SZ  2
#define HD    128
#define DM    4096
#define NROWS (B_SZ * S_LEN)
#define NEGINF (-1e30f)
#define NSPLIT 4

// scratch
__device__ uint32_t g_qh[NROWS * HD / 2];     // [row][d-pair] f16x2, SCALE folded
__device__ uint32_t g_kh[NROWS * HD / 2];     // [row][d-pair] f16x2
__device__ uint32_t g_vt[HD * NROWS / 2];     // [d][global-row-pair] f16x2
__device__ uint32_t g_wt[3 * HD * DM / 2];    // W f16x2, fragment-interleaved groups
__device__ float    g_part[6 * NROWS * HD];   // qkv K-split partials
__device__ float g_opart[NSPLIT * NROWS * HD];
__device__ float g_mpart[NSPLIT * NROWS];
__device__ float g_lpart[NSPLIT * NROWS];

// ---------------- helpers ----------------
__device__ __forceinline__ uint32_t h2(float lo, float hi) {
    uint32_t r;
    asm("cvt.rn.f16x2.f32 %0, %1, %2;" : "=r"(r) : "f"(hi), "f"(lo));
    return r;
}
__device__ __forceinline__ void mma16(float c[4], const uint32_t a[4], const uint32_t b[2]) {
    asm volatile(
        "mma.sync.aligned.m16n8k16.row.col.f32.f16.f16.f32 "
        "{%0,%1,%2,%3}, {%4,%5,%6,%7}, {%8,%9}, {%0,%1,%2,%3};"
        : "+f"(c[0]), "+f"(c[1]), "+f"(c[2]), "+f"(c[3])
        : "r"(a[0]), "r"(a[1]), "r"(a[2]), "r"(a[3]), "r"(b[0]), "r"(b[1]));
}
__device__ __forceinline__ uint32_t smem_u32(const void* p) {
    uint32_t a;
    asm("{ .reg .u64 t; cvta.to.shared.u64 t, %1; cvt.u32.u64 %0, t; }" : "=r"(a) : "l"(p));
    return a;
}
#define CP_ASYNC16(dst_u32, src_ptr) \
    asm volatile("cp.async.cg.shared.global [%0], [%1], 16;" \
                 :: "r"(dst_u32), "l"(src_ptr) : "memory")
#define CP_COMMIT()  asm volatile("cp.async.commit_group;" ::: "memory")
#define CP_WAIT(n)   asm volatile("cp.async.wait_group %0;" :: "n"(n) : "memory")

// ===========================================================================
// Kernel A0: W -> fp16, fragment-interleaved (unchanged)
// ===========================================================================
__global__ __launch_bounds__(256) void wconv_kernel(
    const float* __restrict__ Wq,
    const float* __restrict__ Wk,
    const float* __restrict__ Wv)
{
    const int gid = blockIdx.x * 256 + threadIdx.x;
    const int wi  = gid * 2;
    const int z   = wi >> 18;
    const int r   = wi & 262143;
    const int n   = r >> 11;
    const int wr  = r & 2047;
    const int gs  = wr >> 3;
    const int tp  = (wr & 7) >> 1;
    const float* src = ((z == 0) ? Wq : (z == 1) ? Wk : Wv) + (size_t)n * DM + gs * 16 + 2 * tp;
    const float2 lo = *(const float2*)src;
    const float2 hi = *(const float2*)(src + 8);
    *(uint2*)(g_wt + wi) = make_uint2(h2(lo.x, lo.y), h2(hi.x, hi.y));
}

// ===========================================================================
// Kernel A: QKV projection, fp16 mma, K-split x2 -> fp32 partials (unchanged)
// ===========================================================================
#define PJW 40
#define WJW 24
#define STG 3
#define XSTAGE (128 * PJW)
#define WSTAGE (128 * WJW)
#define PROJ_SMEM (STG * (XSTAGE + WSTAGE) * 4)

__global__ __launch_bounds__(256, 2) void qkv_mma_kernel(const float* __restrict__ x)
{
    extern __shared__ uint32_t smq[];
    uint32_t* Xs = smq;
    uint32_t* Ws = smq + STG * XSTAGE;

    const int t    = threadIdx.x;
    const int lane = t & 31;
    const int w    = t >> 5;
    const int g    = lane >> 2;
    const int tg   = lane & 3;
    const int wm   = w & 3;
    const int wn   = w >> 2;
    const int z    = blockIdx.y;
    const int ks   = blockIdx.z;
    const int m0   = blockIdx.x * 128;
    const int K0   = ks * (DM / 2);
    const int K0w  = ks * (DM / 4);
    const uint32_t* __restrict__ wt = g_wt + (size_t)z * (HD * DM / 2);

    int rowL[4], segL[4];
    uint32_t sbyX[4];
#pragma unroll
    for (int i = 0; i < 4; i++) {
        int idx = i * 256 + t;
        rowL[i] = idx >> 3;
        segL[i] = idx & 7;
        sbyX[i] = (uint32_t)(rowL[i] * PJW + segL[i] * 4) * 4;
    }
    int wrowL[2], wsegL[2];
    uint32_t sbyW[2];
#pragma unroll
    for (int i = 0; i < 2; i++) {
        int idx = i * 256 + t;
        wrowL[i] = idx >> 2;
        wsegL[i] = idx & 3;
        sbyW[i]  = (uint32_t)(wrowL[i] * WJW + wsegL[i] * 4) * 4;
    }
    const uint32_t sxs = smem_u32(Xs);
    const uint32_t sws = smem_u32(Ws);

    float acc[16][4];
#pragma unroll
    for (int n = 0; n < 16; n++)
#pragma unroll
        for (int j = 0; j < 4; j++) acc[n][j] = 0.f;

    const uint32_t am0  = (wm * 32 + g) * PJW;
    const uint32_t am1  = (wm * 32 + 16 + g) * PJW;
    const uint32_t bn0w = (wn * 64 + g) * WJW;

#define ISSUE(c, s) do { \
    const uint32_t _xd = sxs + (s) * (XSTAGE * 4); \
    const uint32_t _wd = sws + (s) * (WSTAGE * 4); \
    _Pragma("unroll") \
    for (int _i = 0; _i < 4; _i++) \
        CP_ASYNC16(_xd + sbyX[_i], x + (size_t)(m0 + rowL[_i]) * DM + K0 + (c) * 32 + segL[_i] * 4); \
    _Pragma("unroll") \
    for (int _i = 0; _i < 2; _i++) \
        CP_ASYNC16(_wd + sbyW[_i], wt + (size_t)wrowL[_i] * (DM / 2) + K0w + (c) * 16 + wsegL[_i] * 4); \
    CP_COMMIT(); \
} while (0)

    ISSUE(0, 0);
    ISSUE(1, 1);

    const int NCH = DM / 64;
    for (int c = 0; c < NCH; c++) {
        if (c == NCH - 1) { CP_WAIT(0); } else { CP_WAIT(1); }
        __syncthreads();
        if (c + 2 < NCH) ISSUE(c + 2, (c + 2) % STG);

        const float*    Xf  = (const float*)(Xs + (c % STG) * XSTAGE);
        const uint32_t* WsS = Ws + (c % STG) * WSTAGE;
#pragma unroll
        for (int s = 0; s < 2; s++) {
            const int kb = s * 16 + 2 * tg;
            float2 p00 = *(const float2*)&Xf[am0 + kb];
            float2 p01 = *(const float2*)&Xf[am0 + kb + 8];
            float2 p02 = *(const float2*)&Xf[am0 + 8 * PJW + kb];
            float2 p03 = *(const float2*)&Xf[am0 + 8 * PJW + kb + 8];
            uint32_t a0[4] = { h2(p00.x, p00.y), h2(p02.x, p02.y),
                               h2(p01.x, p01.y), h2(p03.x, p03.y) };
            float2 p10 = *(const float2*)&Xf[am1 + kb];
            float2 p11 = *(const float2*)&Xf[am1 + kb + 8];
            float2 p12 = *(const float2*)&Xf[am1 + 8 * PJW + kb];
            float2 p13 = *(const float2*)&Xf[am1 + 8 * PJW + kb + 8];
            uint32_t a1[4] = { h2(p10.x, p10.y), h2(p12.x, p12.y),
                               h2(p11.x, p11.y), h2(p13.x, p13.y) };
#pragma unroll
            for (int n8 = 0; n8 < 8; n8++) {
                const uint2 ub = *(const uint2*)&WsS[bn0w + n8 * 8 * WJW + s * 8 + 2 * tg];
                uint32_t bb[2] = { ub.x, ub.y };
                mma16(acc[n8],     a0, bb);
                mma16(acc[8 + n8], a1, bb);
            }
        }
    }
#undef ISSUE

    float* dp = g_part + (size_t)(z * 2 + ks) * NROWS * HD;
#pragma unroll
    for (int mf = 0; mf < 2; mf++) {
        const int r0 = m0 + wm * 32 + mf * 16 + g;
        const int r1 = r0 + 8;
#pragma unroll
        for (int n8 = 0; n8 < 8; n8++) {
            const float* a = acc[mf * 8 + n8];
            const int c = wn * 64 + n8 * 8 + 2 * tg;
            *(float2*)(dp + (size_t)r0 * HD + c) = make_float2(a[0], a[1]);
            *(float2*)(dp + (size_t)r1 * HD + c) = make_float2(a[2], a[3]);
        }
    }
}

// ===========================================================================
// Kernel A2: reduce K-split partials; RoPE + fp16 pack; V transpose (unchanged)
// ===========================================================================
__global__ __launch_bounds__(256) void qkv_reduce()
{
    __shared__ uint32_t st[128 * 68];

    const int t    = threadIdx.x;
    const int z    = blockIdx.y;
    const int rblk = blockIdx.x * 128;
    const int rl   = t >> 1;
    const int hf   = t & 1;
    const int row  = rblk + rl;

    const float* p0 = g_part + (size_t)(2 * z)     * NROWS * HD + (size_t)row * HD;
    const float* p1 = g_part + (size_t)(2 * z + 1) * NROWS * HD + (size_t)row * HD;

    if (z < 2) {
        const float fs   = (z == 0) ? 0.08838834764831845f : 1.0f;
        const float srow = (float)(row & (S_LEN - 1));
#pragma unroll
        for (int i = 0; i < 32; i++) {
            const int p = hf * 32 + i;
            const float2 a0 = *(const float2*)(p0 + 2 * p);
            const float2 a1 = *(const float2*)(p1 + 2 * p);
            const float v0 = a0.x + a1.x;
            const float v1 = a0.y + a1.y;
            const float th = exp2f(-0.4152410118609203f * (float)p);
            float sn, cs;
            sincosf(srow * th, &sn, &cs);
            st[rl * 68 + p] = h2((v0 * cs - v1 * sn) * fs, (v1 * cs + v0 * sn) * fs);
        }
        __syncthreads();
        uint32_t* dsth = (z == 0) ? g_qh : g_kh;
#pragma unroll
        for (int j = 0; j < 32; j++) {
            const int idx = j * 256 + t;
            const int rr = idx >> 6, cc = idx & 63;
            dsth[(size_t)(rblk + rr) * 64 + cc] = st[rr * 68 + cc];
        }
    } else {
        __half* vh = (__half*)st;
#pragma unroll
        for (int i = 0; i < 32; i++) {
            const int p = hf * 32 + i;
            const float2 a0 = *(const float2*)(p0 + 2 * p);
            const float2 a1 = *(const float2*)(p1 + 2 * p);
            vh[(2 * p)     * 132 + rl] = __float2half(a0.x + a1.x);
            vh[(2 * p + 1) * 132 + rl] = __float2half(a0.y + a1.y);
        }
        __syncthreads();
#pragma unroll
        for (int j = 0; j < 32; j++) {
            const int idx = j * 256 + t;
            const int d = idx >> 6, rp = idx & 63;
            g_vt[(size_t)d * (NROWS / 2) + (rblk >> 1) + rp] =
                *(const uint32_t*)&vh[d * 132 + rp * 2];
        }
    }
}

// ===========================================================================
// Kernel B: causal flash attention, fp16 mma. BM=64, 128 threads (4 warps),
// 2 CTAs/SM. NSPLIT-way KV split over 64-key tiles; cp.async double buffer.
// ===========================================================================
#define KSTGW (64 * 68)
#define VSTGW (128 * 36)
#define STGW  (KSTGW + VSTGW)
#define PP_STR 36
#define ATT_SMEM ((2 * STGW + 4 * 16 * PP_STR) * 4)   // 80896 B

__global__ __launch_bounds__(128, 2) void attn_kernel()
{
    extern __shared__ uint32_t sma[];
    uint32_t* Ps = sma + 2 * STGW;

    const int t    = threadIdx.x;
    const int lane = t & 31;
    const int w    = t >> 5;          // 0..3
    const int g    = lane >> 2;
    const int tg   = lane & 3;
    const int b    = blockIdx.y;
    const int h    = blockIdx.z;
    const int qt   = (S_LEN / 64 - 1) - blockIdx.x;   // heavy CTAs first

    const int gr0 = qt * 64 + w * 16 + g;
    const int gr1 = gr0 + 8;
    const int statbase = h * NROWS + b * S_LEN;

    const int ntiles = qt + 1;
    const int cs = (ntiles + NSPLIT - 1) / NSPLIT;
    const int j0 = h * cs;
    const int j1 = min(ntiles, j0 + cs);
    if (j0 >= j1) {
        if (tg == 0) {
            g_mpart[statbase + gr0] = NEGINF; g_lpart[statbase + gr0] = 0.f;
            g_mpart[statbase + gr1] = NEGINF; g_lpart[statbase + gr1] = 0.f;
        }
        return;
    }

    // copy maps: K 1024 16B chunks, V 1024 chunks, 128 threads -> 8 each
    int kkey[8], kseg[8], vd[8], vseg[8];
#pragma unroll
    for (int i = 0; i < 8; i++) {
        int idx = i * 128 + t;
        kkey[i] = idx >> 4; kseg[i] = idx & 15;
        vd[i]   = idx >> 3; vseg[i] = idx & 7;
    }
    const uint32_t sbase = smem_u32(sma);

#define AISSUE(jt, s) do { \
    const size_t _brow = (size_t)b * S_LEN + (size_t)(jt) * 64; \
    const uint32_t _kd = sbase + (s) * (STGW * 4); \
    const uint32_t _vd = _kd + KSTGW * 4; \
    _Pragma("unroll") \
    for (int _i = 0; _i < 8; _i++) { \
        CP_ASYNC16(_kd + kkey[_i] * 272 + kseg[_i] * 16, \
                   g_kh + (_brow + kkey[_i]) * 64 + kseg[_i] * 4); \
        CP_ASYNC16(_vd + vd[_i] * 144 + vseg[_i] * 16, \
                   g_vt + (size_t)vd[_i] * (NROWS / 2) + (_brow >> 1) + vseg[_i] * 4); \
    } \
    CP_COMMIT(); \
} while (0)

    const uint32_t* qw = g_qh + (size_t)b * S_LEN * 64;
    uint32_t qf[8][4];
#pragma unroll
    for (int s = 0; s < 8; s++) {
        qf[s][0] = qw[(size_t)gr0 * 64 + s * 8 + tg];
        qf[s][1] = qw[(size_t)gr1 * 64 + s * 8 + tg];
        qf[s][2] = qw[(size_t)gr0 * 64 + s * 8 + tg + 4];
        qf[s][3] = qw[(size_t)gr1 * 64 + s * 8 + tg + 4];
    }

    float of[16][4];
#pragma unroll
    for (int n = 0; n < 16; n++)
#pragma unroll
        for (int j = 0; j < 4; j++) of[n][j] = 0.f;
    float m0 = NEGINF, m1 = NEGINF, l0 = 0.f, l1 = 0.f;

    uint32_t* pw = &Ps[w * 16 * PP_STR];

    AISSUE(j0, 0);

    for (int jt = j0; jt < j1; jt++) {
        const int buf = (jt - j0) & 1;
        CP_WAIT(0);
        __syncthreads();
        if (jt + 1 < j1) AISSUE(jt + 1, buf ^ 1);

        const uint32_t* Kp = sma + buf * STGW;
        const uint32_t* Vp = Kp + KSTGW;

        float sf[8][4];
#pragma unroll
        for (int n = 0; n < 8; n++)
#pragma unroll
            for (int j = 0; j < 4; j++) sf[n][j] = 0.f;
#pragma unroll
        for (int s = 0; s < 8; s++) {
#pragma unroll
            for (int n8 = 0; n8 < 8; n8++) {
                const uint32_t* kp = &Kp[(n8 * 8 + g) * 68 + s * 8 + tg];
                uint32_t bb[2] = { kp[0], kp[4] };
                mma16(sf[n8], qf[s], bb);
            }
        }

        // causal mask: only the diagonal tile straddles
        if (jt == qt) {
#pragma unroll
            for (int n8 = 0; n8 < 8; n8++) {
                const int c0 = jt * 64 + n8 * 8 + 2 * tg;
                const int c1 = c0 + 1;
                if (c0 > gr0) sf[n8][0] = NEGINF;
                if (c1 > gr0) sf[n8][1] = NEGINF;
                if (c0 > gr1) sf[n8][2] = NEGINF;
                if (c1 > gr1) sf[n8][3] = NEGINF;
            }
        }

        float mx0 = NEGINF, mx1 = NEGINF;
#pragma unroll
        for (int n8 = 0; n8 < 8; n8++) {
            mx0 = fmaxf(mx0, fmaxf(sf[n8][0], sf[n8][1]));
            mx1 = fmaxf(mx1, fmaxf(sf[n8][2], sf[n8][3]));
        }
        mx0 = fmaxf(mx0, __shfl_xor_sync(0xFFFFFFFFu, mx0, 1));
        mx0 = fmaxf(mx0, __shfl_xor_sync(0xFFFFFFFFu, mx0, 2));
        mx1 = fmaxf(mx1, __shfl_xor_sync(0xFFFFFFFFu, mx1, 1));
        mx1 = fmaxf(mx1, __shfl_xor_sync(0xFFFFFFFFu, mx1, 2));

        const float mn0 = fmaxf(m0, mx0);
        const float mn1 = fmaxf(m1, mx1);
        const float al0 = __expf(m0 - mn0);
        const float al1 = __expf(m1 - mn1);

        float sum0 = 0.f, sum1 = 0.f;
#pragma unroll
        for (int n8 = 0; n8 < 8; n8++) {
            sf[n8][0] = __expf(sf[n8][0] - mn0);
            sf[n8][1] = __expf(sf[n8][1] - mn0);
            sf[n8][2] = __expf(sf[n8][2] - mn1);
            sf[n8][3] = __expf(sf[n8][3] - mn1);
            sum0 += sf[n8][0] + sf[n8][1];
            sum1 += sf[n8][2] + sf[n8][3];
        }
        sum0 += __shfl_xor_sync(0xFFFFFFFFu, sum0, 1);
        sum0 += __shfl_xor_sync(0xFFFFFFFFu, sum0, 2);
        sum1 += __shfl_xor_sync(0xFFFFFFFFu, sum1, 1);
        sum1 += __shfl_xor_sync(0xFFFFFFFFu, sum1, 2);
        l0 = l0 * al0 + sum0; m0 = mn0;
        l1 = l1 * al1 + sum1; m1 = mn1;

#pragma unroll
        for (int n8 = 0; n8 < 8; n8++) {
            pw[g * PP_STR + n8 * 4 + tg]       = h2(sf[n8][0], sf[n8][1]);
            pw[(g + 8) * PP_STR + n8 * 4 + tg] = h2(sf[n8][2], sf[n8][3]);
        }
        __syncwarp();

#pragma unroll
        for (int n8 = 0; n8 < 16; n8++) {
            of[n8][0] *= al0; of[n8][1] *= al0;
            of[n8][2] *= al1; of[n8][3] *= al1;
        }

#pragma unroll
        for (int s = 0; s < 4; s++) {
            uint32_t af[4];
            af[0] = pw[g * PP_STR + s * 8 + tg];
            af[1] = pw[(g + 8) * PP_STR + s * 8 + tg];
            af[2] = pw[g * PP_STR + s * 8 + tg + 4];
            af[3] = pw[(g + 8) * PP_STR + s * 8 + tg + 4];
#pragma unroll
            for (int n8 = 0; n8 < 16; n8++) {
                const uint32_t* vp = &Vp[(n8 * 8 + g) * 36 + s * 8 + tg];
                uint32_t bb[2] = { vp[0], vp[4] };
                mma16(of[n8], af, bb);
            }
        }
    }
#undef AISSUE

    const float inv0 = (l0 > 0.f) ? 1.0f / l0 : 0.f;
    const float inv1 = (l1 > 0.f) ? 1.0f / l1 : 0.f;
    float* ob = g_opart + ((size_t)h * NROWS + (size_t)b * S_LEN) * HD;
#pragma unroll
    for (int n8 = 0; n8 < 16; n8++) {
        const int c = n8 * 8 + 2 * tg;
        *(float2*)(ob + (size_t)gr0 * HD + c) = make_float2(of[n8][0] * inv0, of[n8][1] * inv0);
        *(float2*)(ob + (size_t)gr1 * HD + c) = make_float2(of[n8][2] * inv1, of[n8][3] * inv1);
    }
    if (tg == 0) {
        g_mpart[statbase + gr0] = m0; g_lpart[statbase + gr0] = l0;
        g_mpart[statbase + gr1] = m1; g_lpart[statbase + gr1] = l1;
    }
}

// ===========================================================================
// Kernel C: combine the NSPLIT partial-softmax results (unchanged)
// ===========================================================================
__global__ __launch_bounds__(256) void combine_kernel(float* __restrict__ out)
{
    const int idx = blockIdx.x * 256 + threadIdx.x;
    const int row = idx >> 5;
    const int c4  = idx & 31;

    float mh[NSPLIT], lh[NSPLIT];
    float M = NEGINF;
#pragma unroll
    for (int h = 0; h < NSPLIT; h++) {
        mh[h] = g_mpart[h * NROWS + row];
        lh[h] = g_lpart[h * NROWS + row];
        M = fmaxf(M, mh[h]);
    }
    float wsum = 0.f, wh[NSPLIT];
#pragma unroll
    for (int h = 0; h < NSPLIT; h++) {
        wh[h] = lh[h] * __expf(mh[h] - M);
        wsum += wh[h];
    }
    const float inv = 1.0f / wsum;

    const size_t off = ((size_t)row << 7) + (c4 << 2);
    float4 r = make_float4(0.f, 0.f, 0.f, 0.f);
#pragma unroll
    for (int h = 0; h < NSPLIT; h++) {
        const float wn = wh[h] * inv;
        if (wn > 0.f) {
            const float4 a = *(const float4*)(g_opart + (size_t)h * NROWS * HD + off);
            r.x += wn * a.x; r.y += wn * a.y; r.z += wn * a.z; r.w += wn * a.w;
        }
    }
    *(float4*)(out + off) = r;
}

// ===========================================================================
extern "C" void kernel_launch(void* const* d_in, const int* in_sizes, int n_in,
                              void* d_out, int out_size)
{
    const float* x  = (const float*)d_in[0];
    const float* Wq = (const float*)d_in[1];
    const float* Wk = (const float*)d_in[2];
    const float* Wv = (const float*)d_in[3];
    float* out = (float*)d_out;

    cudaFuncSetAttribute(qkv_mma_kernel, cudaFuncAttributeMaxDynamicSharedMemorySize, PROJ_SMEM);
    cudaFuncSetAttribute(attn_kernel,    cudaFuncAttributeMaxDynamicSharedMemorySize, ATT_SMEM);

    wconv_kernel<<<1536, 256>>>(Wq, Wk, Wv);
    qkv_mma_kernel<<<dim3(NROWS / 128, 3, 2), 256, PROJ_SMEM>>>(x);
    qkv_reduce<<<dim3(NROWS / 128, 3), 256>>>();
    attn_kernel<<<dim3(S_LEN / 64, B_SZ, NSPLIT), 128, ATT_SMEM>>>();
    combine_kernel<<<(NROWS * 32) / 256, 256>>>(out);
}